// round 7
// baseline (speedup 1.0000x reference)
#include <cuda_runtime.h>

#define NB   16
#define NF   64
#define LATD 512
#define IMG  64
#define HWD  4096
#define FIN  576
#define PD   78016
#define CATD 2048

#define OFF_KIN  0
#define OFF_BIN  36864
#define OFF_KOUT 36928
#define OFF_BOUT 41024
#define OFF_KSK  41088
#define OFF_BSK  77952

#define PTS  77824   // per-batch transposed-params stride: 36864*2 + 4096
#define TN   128
#define KCH  16

typedef unsigned long long ull;

// ---------------- scratch (device globals; no allocs allowed) ----------------
__device__ float g_out [NB*NF*HWD];
__device__ float g_feat[(size_t)NB*FIN*HWD];
__device__ float g_p   [NB*PD];
__device__ float g_pt  [NB*PTS];
__device__ float g_injA[NB*LATD], g_injB[NB*LATD];
__device__ float g_latA[NB*LATD], g_latB[NB*LATD];
__device__ float g_t512[NB*LATD];
__device__ float g_cat [NB*CATD];
__device__ float g_t2048[NB*CATD];
__device__ float g_part[16*NB*CATD];

__device__ __forceinline__ float lrelu(float v){ return v > 0.f ? v : 0.2f*v; }

__device__ __forceinline__ void ffma2(ull& d, ull a, ull b){
    asm("fma.rn.f32x2 %0, %1, %2, %0;" : "+l"(d) : "l"(a), "l"(b));
}
__device__ __forceinline__ ull dup2(float v){
    ull r; asm("mov.b64 %0, {%1, %1};" : "=l"(r) : "f"(v)); return r;
}
__device__ __forceinline__ ull pack2(float lo, float hi){
    ull r; asm("mov.b64 %0, {%1, %2};" : "=l"(r) : "f"(lo), "f"(hi)); return r;
}
__device__ __forceinline__ void unpack2(ull v, float& lo, float& hi){
    asm("mov.b64 {%0, %1}, %2;" : "=f"(lo), "=f"(hi) : "l"(v));
}

// ---------------- out0 = w_in @ x + b_in ----------------
__global__ void k_init_out(const float* __restrict__ x, const float* __restrict__ w_in,
                           const float* __restrict__ b_in, float* __restrict__ out){
    int b = blockIdx.x >> 6, o = blockIdx.x & 63;
    float w0 = w_in[o*3+0], w1 = w_in[o*3+1], w2 = w_in[o*3+2], bb = b_in[o];
    const float* xb = x + (size_t)b*3*HWD;
    float* ob = out + (size_t)blockIdx.x*HWD;
    for (int p = threadIdx.x; p < HWD; p += blockDim.x)
        ob[p] = w0*xb[p] + w1*xb[HWD+p] + w2*xb[2*HWD+p] + bb;
}

__global__ void k_zero(float* p){ p[blockIdx.x*512 + threadIdx.x] = 0.f; }

__global__ void k_copylat(const float* __restrict__ lat, float* __restrict__ cat){
    int idx = blockIdx.x*256 + threadIdx.x;
    int b = idx >> 9, n = idx & 511;
    cat[b*CATD + n] = lat[idx];
}

// ---------------- small GEMMs: Y(16,N) = X(16,K) @ W(K,N) ----------------
__global__ void __launch_bounds__(128) gemm16_part(
    const float* __restrict__ X, int K, const float* __restrict__ W,
    float* __restrict__ Yp, int N, int kc, int slot0)
{
    __shared__ __align__(16) float Xs[256*16];
    int ks = blockIdx.y;
    int k0 = ks*kc;
    int klen = min(kc, K - k0);
    for (int k = threadIdx.x; k < klen; k += 128){
        #pragma unroll
        for (int b = 0; b < 16; b++) Xs[k*16+b] = X[(size_t)b*K + k0 + k];
    }
    __syncthreads();
    int n = blockIdx.x*128 + threadIdx.x;
    if (n >= N) return;
    float acc[16];
    #pragma unroll
    for (int b = 0; b < 16; b++) acc[b] = 0.f;
    #pragma unroll 4
    for (int k = 0; k < klen; k++){
        float w = W[(size_t)(k0+k)*N + n];
        const float4* xp = (const float4*)(Xs + k*16);
        float4 x0 = xp[0], x1 = xp[1], x2 = xp[2], x3 = xp[3];
        acc[0]+=x0.x*w; acc[1]+=x0.y*w; acc[2]+=x0.z*w; acc[3]+=x0.w*w;
        acc[4]+=x1.x*w; acc[5]+=x1.y*w; acc[6]+=x1.z*w; acc[7]+=x1.w*w;
        acc[8]+=x2.x*w; acc[9]+=x2.y*w; acc[10]+=x2.z*w; acc[11]+=x2.w*w;
        acc[12]+=x3.x*w; acc[13]+=x3.y*w; acc[14]+=x3.z*w; acc[15]+=x3.w*w;
    }
    float* yp = Yp + (size_t)(slot0+ks)*16*N;
    #pragma unroll
    for (int b = 0; b < 16; b++) yp[(size_t)b*N + n] = acc[b];
}

__global__ void gemm16_reduce(const float* __restrict__ Yp, int nslots,
                              const float* __restrict__ b1, const float* __restrict__ b2,
                              float* __restrict__ Y, int N, int leaky)
{
    int idx = blockIdx.x*256 + threadIdx.x;
    if (idx >= 16*N) return;
    int n = idx % N;
    float s = 0.f;
    for (int t = 0; t < nslots; t++) s += Yp[(size_t)t*16*N + idx];
    if (b1) s += b1[n];
    if (b2) s += b2[n];
    if (leaky) s = lrelu(s);
    Y[idx] = s;
}

__global__ void __launch_bounds__(128) gemm16_full(
    const float* __restrict__ X, int K, const float* __restrict__ W,
    const float* __restrict__ bias, float* __restrict__ Y, int N)
{
    __shared__ __align__(16) float Xs[512*16];
    for (int k = threadIdx.x; k < K; k += 128){
        #pragma unroll
        for (int b = 0; b < 16; b++) Xs[k*16+b] = X[(size_t)b*K + k];
    }
    __syncthreads();
    int n = blockIdx.x*128 + threadIdx.x;
    if (n >= N) return;
    float acc[16];
    #pragma unroll
    for (int b = 0; b < 16; b++) acc[b] = 0.f;
    #pragma unroll 8
    for (int k = 0; k < K; k++){
        float w = W[(size_t)k*N + n];
        const float4* xp = (const float4*)(Xs + k*16);
        float4 x0 = xp[0], x1 = xp[1], x2 = xp[2], x3 = xp[3];
        acc[0]+=x0.x*w; acc[1]+=x0.y*w; acc[2]+=x0.z*w; acc[3]+=x0.w*w;
        acc[4]+=x1.x*w; acc[5]+=x1.y*w; acc[6]+=x1.z*w; acc[7]+=x1.w*w;
        acc[8]+=x2.x*w; acc[9]+=x2.y*w; acc[10]+=x2.z*w; acc[11]+=x2.w*w;
        acc[12]+=x3.x*w; acc[13]+=x3.y*w; acc[14]+=x3.z*w; acc[15]+=x3.w*w;
    }
    float bv = bias[n];
    #pragma unroll
    for (int b = 0; b < 16; b++) Y[(size_t)b*N + n] = acc[b] + bv;
}

// ---------------- transpose dynamic weights: p -> pt ----------------
// kinT[i][f], kskT[i][f] (576x64), koutT[k][m] (64x64)
__global__ void k_prep(const float* __restrict__ p, float* __restrict__ pt){
    __shared__ float t[32][33];
    int b = blockIdx.z, mat = blockIdx.y;
    int cols = (mat == 2) ? 64 : FIN;
    int ntx = cols / 32;
    int ntiles = 2 * ntx;             // 64 rows / 32
    int tile = blockIdx.x;
    if (tile >= ntiles) return;
    int tf = tile / ntx, ti = tile % ntx;
    int srcoff = (mat == 0) ? OFF_KIN : (mat == 1) ? OFF_KSK : OFF_KOUT;
    int dstoff = (mat == 0) ? 0 : (mat == 1) ? 36864 : 73728;
    const float* src = p + (size_t)b*PD + srcoff;
    float* dst = pt + (size_t)b*PTS + dstoff;
    int f0 = tf*32, i0 = ti*32;
    for (int r = threadIdx.y; r < 32; r += 8)
        t[r][threadIdx.x] = src[(f0+r)*cols + i0 + threadIdx.x];
    __syncthreads();
    for (int r = threadIdx.y; r < 32; r += 8)
        dst[(i0+r)*64 + f0 + threadIdx.x] = t[threadIdx.x][r];
}

// ---------------- perceive (dilated Sobel bank) + instance norm ----------------
__global__ void __launch_bounds__(256) k_perceive(const float* __restrict__ out,
                                                  float* __restrict__ feat){
    __shared__ float xs[64*64];
    __shared__ float rs1[8], rs2[8], bcast[2];
    int bcid = blockIdx.x;
    int b = bcid >> 6, c = bcid & 63;
    const float* src = out + (size_t)bcid*HWD;
    for (int p = threadIdx.x; p < HWD; p += 256) xs[p] = src[p];
    __syncthreads();
    int lane = threadIdx.x & 31, wrp = threadIdx.x >> 5;
    for (int g = 0; g < 9; g++){
        float v[16];
        float s1 = 0.f, s2 = 0.f;
        int d = (g == 0) ? 0 : (1 << ((g-1) >> 1));
        int isX = ((g-1) & 1) == 0;
        #pragma unroll
        for (int t = 0; t < 16; t++){
            int p = threadIdx.x + t*256;
            int i = p >> 6, j = p & 63;
            float val;
            if (g == 0){
                val = xs[p];
            } else {
                int im = i-d, ip = i+d, jm = j-d, jp = j+d;
                bool imv = im >= 0, ipv = ip < 64, jmv = jm >= 0, jpv = jp < 64;
                if (isX){
                    float t0 = ((imv&&jpv) ? xs[im*64+jp] : 0.f) - ((imv&&jmv) ? xs[im*64+jm] : 0.f);
                    float t1 = (jpv ? xs[i*64+jp] : 0.f)         - (jmv ? xs[i*64+jm] : 0.f);
                    float t2 = ((ipv&&jpv) ? xs[ip*64+jp] : 0.f) - ((ipv&&jmv) ? xs[ip*64+jm] : 0.f);
                    val = 0.125f*(t0 + 2.f*t1 + t2);
                } else {
                    float t0 = ((ipv&&jmv) ? xs[ip*64+jm] : 0.f) - ((imv&&jmv) ? xs[im*64+jm] : 0.f);
                    float t1 = (ipv ? xs[ip*64+j] : 0.f)         - (imv ? xs[im*64+j] : 0.f);
                    float t2 = ((ipv&&jpv) ? xs[ip*64+jp] : 0.f) - ((imv&&jpv) ? xs[im*64+jp] : 0.f);
                    val = 0.125f*(t0 + 2.f*t1 + t2);
                }
            }
            v[t] = val; s1 += val; s2 += val*val;
        }
        #pragma unroll
        for (int s = 16; s > 0; s >>= 1){
            s1 += __shfl_xor_sync(0xffffffffu, s1, s);
            s2 += __shfl_xor_sync(0xffffffffu, s2, s);
        }
        if (lane == 0){ rs1[wrp] = s1; rs2[wrp] = s2; }
        __syncthreads();
        if (threadIdx.x == 0){
            float a = 0.f, q = 0.f;
            #pragma unroll
            for (int w = 0; w < 8; w++){ a += rs1[w]; q += rs2[w]; }
            float mean = a*(1.f/4096.f);
            float var  = q*(1.f/4096.f) - mean*mean;
            bcast[0] = mean; bcast[1] = rsqrtf(var + 1e-5f);
        }
        __syncthreads();
        float mean = bcast[0], inv = bcast[1];
        float* dst = feat + ((size_t)b*FIN + g*64 + c)*HWD;
        #pragma unroll
        for (int t = 0; t < 16; t++)
            dst[threadIdx.x + t*256] = (v[t]-mean)*inv;
    }
}

// ---------------- fused dynamic conv: h + skip + out in one kernel ----------------
// Block: 256 threads, tile = (batch b, 128 spatial cols). FFMA2 throughout.
// smem: As2i[16][128] dup, As2s[16][128] dup, Bs[16][128], Hs[64][128] = 56KB dyn.
__global__ void __launch_bounds__(256, 2) k_dyn(
    const float* __restrict__ pt, const float* __restrict__ p,
    const float* __restrict__ feat, float* __restrict__ outp)
{
    extern __shared__ float sm[];
    float* As2i = sm;            // 2048
    float* As2s = sm + 2048;     // 2048
    float* Bs   = sm + 4096;     // 2048
    float* Hs   = sm + 6144;     // 8192

    int b = blockIdx.y, n0 = blockIdx.x*TN;
    int tid = threadIdx.x;
    int tn = tid & 31, tm = tid >> 5;           // tn: 32 col-pair groups, tm: 8 m-groups
    int rF = tid >> 4, cF8 = (tid & 15) * 8;    // B fill
    int cF4 = (tid & 15) * 4;                   // A fill

    const float* featb = feat + (size_t)b*FIN*HWD + n0;
    const float* kinT  = pt + (size_t)b*PTS;
    const float* kskT  = kinT + 36864;
    const float* koutT = kinT + 73728;
    const float* pb    = p + (size_t)b*PD;

    ull accH[8][2], accS[8][2];
    #pragma unroll
    for (int r = 0; r < 8; r++){
        accH[r][0] = 0ull; accH[r][1] = 0ull;
        accS[r][0] = 0ull; accS[r][1] = 0ull;
    }

    // ---- phase A: accH += k_in @ feat ; accS += k_sk @ feat (single feat pass) ----
    for (int k0 = 0; k0 < FIN; k0 += KCH){
        float4 bv0 = *(const float4*)(featb + (size_t)(k0 + rF)*HWD + cF8);
        float4 bv1 = *(const float4*)(featb + (size_t)(k0 + rF)*HWD + cF8 + 4);
        float4 avi = *(const float4*)(kinT + (k0 + rF)*64 + cF4);
        float4 avs = *(const float4*)(kskT + (k0 + rF)*64 + cF4);
        __syncthreads();
        *(float4*)(Bs + rF*TN + cF8)     = bv0;
        *(float4*)(Bs + rF*TN + cF8 + 4) = bv1;
        ull* ai = (ull*)(As2i + rF*128 + 2*cF4);
        ai[0] = dup2(avi.x); ai[1] = dup2(avi.y); ai[2] = dup2(avi.z); ai[3] = dup2(avi.w);
        ull* as = (ull*)(As2s + rF*128 + 2*cF4);
        as[0] = dup2(avs.x); as[1] = dup2(avs.y); as[2] = dup2(avs.z); as[3] = dup2(avs.w);
        __syncthreads();
        #pragma unroll
        for (int k = 0; k < KCH; k++){
            ull b0 = *(const ull*)(Bs + k*TN + 2*tn);
            ull b1 = *(const ull*)(Bs + k*TN + 64 + 2*tn);
            #pragma unroll
            for (int r = 0; r < 8; r++){
                ull aI = *(const ull*)(As2i + k*128 + 2*(tm*8 + r));
                ull aS = *(const ull*)(As2s + k*128 + 2*(tm*8 + r));
                ffma2(accH[r][0], aI, b0); ffma2(accH[r][1], aI, b1);
                ffma2(accS[r][0], aS, b0); ffma2(accS[r][1], aS, b1);
            }
        }
    }

    // ---- write h = lrelu(accH + b_in) into smem Hs ----
    #pragma unroll
    for (int r = 0; r < 8; r++){
        int m = tm*8 + r;
        float bin = pb[OFF_BIN + m];
        #pragma unroll
        for (int j = 0; j < 2; j++){
            float lo, hi; unpack2(accH[r][j], lo, hi);
            lo = lrelu(lo + bin); hi = lrelu(hi + bin);
            *(ull*)(Hs + m*TN + j*64 + 2*tn) = pack2(lo, hi);
        }
    }

    // ---- phase B: accS += k_out @ h (h in smem) ----
    for (int k0 = 0; k0 < 64; k0 += KCH){
        float4 avo = *(const float4*)(koutT + (k0 + rF)*64 + cF4);
        __syncthreads();
        ull* ao = (ull*)(As2i + rF*128 + 2*cF4);
        ao[0] = dup2(avo.x); ao[1] = dup2(avo.y); ao[2] = dup2(avo.z); ao[3] = dup2(avo.w);
        __syncthreads();
        #pragma unroll
        for (int k = 0; k < KCH; k++){
            ull b0 = *(const ull*)(Hs + (k0+k)*TN + 2*tn);
            ull b1 = *(const ull*)(Hs + (k0+k)*TN + 64 + 2*tn);
            #pragma unroll
            for (int r = 0; r < 8; r++){
                ull aO = *(const ull*)(As2i + k*128 + 2*(tm*8 + r));
                ffma2(accS[r][0], aO, b0); ffma2(accS[r][1], aO, b1);
            }
        }
    }

    // ---- out = accS + b_out + b_sk ----
    #pragma unroll
    for (int r = 0; r < 8; r++){
        int m = tm*8 + r;
        float bias = pb[OFF_BOUT + m] + pb[OFF_BSK + m];
        float* dst = outp + ((size_t)(b*NF + m))*HWD + n0;
        #pragma unroll
        for (int j = 0; j < 2; j++){
            float lo, hi; unpack2(accS[r][j], lo, hi);
            *(ull*)(dst + j*64 + 2*tn) = pack2(lo + bias, hi + bias);
        }
    }
}

// ---------------- freq = (out . pe) / 4096 into cat[:, 512:] ----------------
__global__ void __launch_bounds__(128) k_freq(const float* __restrict__ out,
                                              const float* __restrict__ pe,
                                              float* __restrict__ cat){
    int b = blockIdx.y;
    int c0 = blockIdx.x*4;
    const float* o0 = out + ((size_t)b*NF + c0)*HWD;
    float acc[4][24];
    #pragma unroll
    for (int ch = 0; ch < 4; ch++)
        #pragma unroll
        for (int f = 0; f < 24; f++) acc[ch][f] = 0.f;
    for (int p = threadIdx.x; p < HWD; p += 128){
        float ov0 = o0[p], ov1 = o0[HWD+p], ov2 = o0[2*HWD+p], ov3 = o0[3*HWD+p];
        #pragma unroll
        for (int f = 0; f < 24; f++){
            float pv = pe[f*HWD + p];
            acc[0][f] += ov0*pv; acc[1][f] += ov1*pv;
            acc[2][f] += ov2*pv; acc[3][f] += ov3*pv;
        }
    }
    __shared__ float red[4][4][24];
    int lane = threadIdx.x & 31, wrp = threadIdx.x >> 5;
    #pragma unroll
    for (int ch = 0; ch < 4; ch++)
        #pragma unroll
        for (int f = 0; f < 24; f++){
            float v = acc[ch][f];
            #pragma unroll
            for (int s = 16; s > 0; s >>= 1) v += __shfl_xor_sync(0xffffffffu, v, s);
            if (lane == 0) red[wrp][ch][f] = v;
        }
    __syncthreads();
    if (threadIdx.x < 96){
        int ch = threadIdx.x / 24, f = threadIdx.x % 24;
        float s = red[0][ch][f] + red[1][ch][f] + red[2][ch][f] + red[3][ch][f];
        cat[b*CATD + 512 + (c0+ch)*24 + f] = s * (1.f/4096.f);
    }
}

// ---------------- host orchestration ----------------
extern "C" void kernel_launch(void* const* d_in, const int* in_sizes, int n_in,
                              void* d_out, int out_size){
    const float* x      = (const float*)d_in[0];
    const float* inj    = (const float*)d_in[1];
    const float* w_in   = (const float*)d_in[2];
    const float* b_in   = (const float*)d_in[3];
    const float* fl_w1  = (const float*)d_in[4];
    const float* fl_b1  = (const float*)d_in[5];
    const float* fl_w2  = (const float*)d_in[6];
    const float* fl_b2  = (const float*)d_in[7];
    const float* fl_ws  = (const float*)d_in[8];
    const float* fl_bs  = (const float*)d_in[9];
    const float* dyn_w  = (const float*)d_in[10];
    const float* dyn_b  = (const float*)d_in[11];
    const float* pe     = (const float*)d_in[12];
    const float* otl_w1 = (const float*)d_in[13];
    const float* otl_b1 = (const float*)d_in[14];
    const float* otl_w2 = (const float*)d_in[15];
    const float* otl_b2 = (const float*)d_in[16];
    const float* otl_ws = (const float*)d_in[17];
    const float* otl_bs = (const float*)d_in[18];
    const float* ltl_w  = (const float*)d_in[19];
    const float* ltl_b  = (const float*)d_in[20];

    float *p_out, *p_feat, *p_p, *p_pt, *p_injA, *p_injB, *p_latA, *p_latB;
    float *p_t512, *p_cat, *p_t2048, *p_part;
    cudaGetSymbolAddress((void**)&p_out,  g_out);
    cudaGetSymbolAddress((void**)&p_feat, g_feat);
    cudaGetSymbolAddress((void**)&p_p,    g_p);
    cudaGetSymbolAddress((void**)&p_pt,   g_pt);
    cudaGetSymbolAddress((void**)&p_injA, g_injA);
    cudaGetSymbolAddress((void**)&p_injB, g_injB);
    cudaGetSymbolAddress((void**)&p_latA, g_latA);
    cudaGetSymbolAddress((void**)&p_latB, g_latB);
    cudaGetSymbolAddress((void**)&p_t512, g_t512);
    cudaGetSymbolAddress((void**)&p_cat,  g_cat);
    cudaGetSymbolAddress((void**)&p_t2048,g_t2048);
    cudaGetSymbolAddress((void**)&p_part, g_part);

    static int smem_set = 0;
    if (!smem_set){
        cudaFuncSetAttribute(k_dyn, cudaFuncAttributeMaxDynamicSharedMemorySize, 57344);
        smem_set = 1;
    }

    cudaMemcpyAsync(p_injA, inj, (size_t)NB*LATD*sizeof(float), cudaMemcpyDeviceToDevice);
    k_zero<<<16, 512>>>(p_latA);
    k_init_out<<<NB*NF, 256>>>(x, w_in, b_in, p_out);

    float* injC = p_injA; float* injN = p_injB;
    float* latC = p_latA; float* latN = p_latB;

    for (int c = 0; c < 4; c++){
        // inj_lat = lin_res(inj_lat, fl_*)
        gemm16_part<<<dim3(4,8), 128>>>(injC, LATD, fl_w1, p_part, LATD, 64, 0);
        gemm16_reduce<<<32, 256>>>(p_part, 8, fl_b1, nullptr, p_t512, LATD, 1);
        gemm16_part<<<dim3(4,8), 128>>>(injC, LATD, fl_ws, p_part, LATD, 64, 0);
        gemm16_part<<<dim3(4,8), 128>>>(p_t512, LATD, fl_w2, p_part, LATD, 64, 8);
        gemm16_reduce<<<32, 256>>>(p_part, 16, fl_bs, fl_b2, injN, LATD, 0);

        // p = inj_lat @ dyn_w + dyn_b; transpose dynamic kernels
        gemm16_full<<<(PD + 127)/128, 128>>>(injN, LATD, dyn_w, dyn_b, p_p, PD);
        k_prep<<<dim3(36, 3, NB), dim3(32, 8)>>>(p_p, p_pt);

        // feat = inorm(perceive(out))
        k_perceive<<<NB*NF, 256>>>(p_out, p_feat);

        // fused dynamic conv (h + out in one pass over feat)
        k_dyn<<<dim3(HWD/TN, NB), 256, 57344>>>(p_pt, p_p, p_feat, p_out);

        // cat = [lat, freq]
        k_freq<<<dim3(16, NB), 128>>>(p_out, pe, p_cat);
        k_copylat<<<32, 256>>>(latC, p_cat);

        // lat = lin_res(cat, otl_*[c])
        const float* w1 = otl_w1 + (size_t)c*CATD*CATD;
        const float* b1 = otl_b1 + (size_t)c*CATD;
        const float* w2 = otl_w2 + (size_t)c*CATD*LATD;
        const float* b2 = otl_b2 + (size_t)c*LATD;
        const float* ws = otl_ws + (size_t)c*CATD*LATD;
        const float* bs = otl_bs + (size_t)c*LATD;
        gemm16_part<<<dim3(16,8), 128>>>(p_cat, CATD, w1, p_part, CATD, 256, 0);
        gemm16_reduce<<<128, 256>>>(p_part, 8, b1, nullptr, p_t2048, CATD, 1);
        gemm16_part<<<dim3(4,8), 128>>>(p_cat, CATD, ws, p_part, LATD, 256, 0);
        gemm16_part<<<dim3(4,8), 128>>>(p_t2048, CATD, w2, p_part, LATD, 256, 8);
        gemm16_reduce<<<32, 256>>>(p_part, 16, bs, b2, latN, LATD, 0);

        float* t;
        t = injC; injC = injN; injN = t;
        t = latC; latC = latN; latN = t;
    }

    // out = lat @ ltl_w + ltl_b
    gemm16_part<<<dim3(4,8), 128>>>(latC, LATD, ltl_w, p_part, LATD, 64, 0);
    gemm16_reduce<<<32, 256>>>(p_part, 8, ltl_b, nullptr, (float*)d_out, LATD, 0);
}

// round 8
// speedup vs baseline: 1.0232x; 1.0232x over previous
#include <cuda_runtime.h>

#define NB   16
#define NF   64
#define LATD 512
#define IMG  64
#define HWD  4096
#define FIN  576
#define PD   78016
#define CATD 2048

#define OFF_KIN  0
#define OFF_BIN  36864
#define OFF_KOUT 36928
#define OFF_BOUT 41024
#define OFF_KSK  41088
#define OFF_BSK  77952

#define PTS  77824   // per-batch transposed-params stride
#define DTN  256     // dyn-GEMM N tile
#define DKC  32      // dyn-GEMM K chunk

typedef unsigned long long ull;

// ---------------- scratch (device globals; no allocs allowed) ----------------
__device__ float g_out [NB*NF*HWD];
__device__ float g_feat[(size_t)NB*FIN*HWD];
__device__ float g_h   [NB*NF*HWD];
__device__ float g_p   [NB*PD];
__device__ float g_pt  [NB*PTS];
__device__ float g_injA[NB*LATD], g_injB[NB*LATD];
__device__ float g_latA[NB*LATD], g_latB[NB*LATD];
__device__ float g_t512[NB*LATD];
__device__ float g_cat [NB*CATD];
__device__ float g_t2048[NB*CATD];
__device__ float g_part[16*NB*CATD];

__device__ __forceinline__ float lrelu(float v){ return v > 0.f ? v : 0.2f*v; }

__device__ __forceinline__ void ffma2(ull& d, ull a, ull b){
    asm("fma.rn.f32x2 %0, %1, %2, %0;" : "+l"(d) : "l"(a), "l"(b));
}
__device__ __forceinline__ ull dup2(float v){
    ull r; asm("mov.b64 %0, {%1, %1};" : "=l"(r) : "f"(v)); return r;
}
__device__ __forceinline__ ull pack2(float lo, float hi){
    ull r; asm("mov.b64 %0, {%1, %2};" : "=l"(r) : "f"(lo), "f"(hi)); return r;
}
__device__ __forceinline__ void unpack2(ull v, float& lo, float& hi){
    asm("mov.b64 {%0, %1}, %2;" : "=f"(lo), "=f"(hi) : "l"(v));
}

// ---------------- out0 = w_in @ x + b_in ----------------
__global__ void k_init_out(const float* __restrict__ x, const float* __restrict__ w_in,
                           const float* __restrict__ b_in, float* __restrict__ out){
    int b = blockIdx.x >> 6, o = blockIdx.x & 63;
    float w0 = w_in[o*3+0], w1 = w_in[o*3+1], w2 = w_in[o*3+2], bb = b_in[o];
    const float* xb = x + (size_t)b*3*HWD;
    float* ob = out + (size_t)blockIdx.x*HWD;
    for (int p = threadIdx.x; p < HWD; p += blockDim.x)
        ob[p] = w0*xb[p] + w1*xb[HWD+p] + w2*xb[2*HWD+p] + bb;
}

__global__ void k_zero(float* p){ p[blockIdx.x*512 + threadIdx.x] = 0.f; }

__global__ void k_copylat(const float* __restrict__ lat, float* __restrict__ cat){
    int idx = blockIdx.x*256 + threadIdx.x;
    int b = idx >> 9, n = idx & 511;
    cat[b*CATD + n] = lat[idx];
}

// ---------------- small GEMMs: Y(16,N) = X(16,K) @ W(K,N) ----------------
__global__ void __launch_bounds__(128) gemm16_part(
    const float* __restrict__ X, int K, const float* __restrict__ W,
    float* __restrict__ Yp, int N, int kc, int slot0)
{
    __shared__ __align__(16) float Xs[256*16];
    int ks = blockIdx.y;
    int k0 = ks*kc;
    int klen = min(kc, K - k0);
    for (int k = threadIdx.x; k < klen; k += 128){
        #pragma unroll
        for (int b = 0; b < 16; b++) Xs[k*16+b] = X[(size_t)b*K + k0 + k];
    }
    __syncthreads();
    int n = blockIdx.x*128 + threadIdx.x;
    if (n >= N) return;
    float acc[16];
    #pragma unroll
    for (int b = 0; b < 16; b++) acc[b] = 0.f;
    #pragma unroll 4
    for (int k = 0; k < klen; k++){
        float w = W[(size_t)(k0+k)*N + n];
        const float4* xp = (const float4*)(Xs + k*16);
        float4 x0 = xp[0], x1 = xp[1], x2 = xp[2], x3 = xp[3];
        acc[0]+=x0.x*w; acc[1]+=x0.y*w; acc[2]+=x0.z*w; acc[3]+=x0.w*w;
        acc[4]+=x1.x*w; acc[5]+=x1.y*w; acc[6]+=x1.z*w; acc[7]+=x1.w*w;
        acc[8]+=x2.x*w; acc[9]+=x2.y*w; acc[10]+=x2.z*w; acc[11]+=x2.w*w;
        acc[12]+=x3.x*w; acc[13]+=x3.y*w; acc[14]+=x3.z*w; acc[15]+=x3.w*w;
    }
    float* yp = Yp + (size_t)(slot0+ks)*16*N;
    #pragma unroll
    for (int b = 0; b < 16; b++) yp[(size_t)b*N + n] = acc[b];
}

__global__ void gemm16_reduce(const float* __restrict__ Yp, int nslots,
                              const float* __restrict__ b1, const float* __restrict__ b2,
                              float* __restrict__ Y, int N, int leaky)
{
    int idx = blockIdx.x*256 + threadIdx.x;
    if (idx >= 16*N) return;
    int n = idx % N;
    float s = 0.f;
    for (int t = 0; t < nslots; t++) s += Yp[(size_t)t*16*N + idx];
    if (b1) s += b1[n];
    if (b2) s += b2[n];
    if (leaky) s = lrelu(s);
    Y[idx] = s;
}

__global__ void __launch_bounds__(128) gemm16_full(
    const float* __restrict__ X, int K, const float* __restrict__ W,
    const float* __restrict__ bias, float* __restrict__ Y, int N)
{
    __shared__ __align__(16) float Xs[512*16];
    for (int k = threadIdx.x; k < K; k += 128){
        #pragma unroll
        for (int b = 0; b < 16; b++) Xs[k*16+b] = X[(size_t)b*K + k];
    }
    __syncthreads();
    int n = blockIdx.x*128 + threadIdx.x;
    if (n >= N) return;
    float acc[16];
    #pragma unroll
    for (int b = 0; b < 16; b++) acc[b] = 0.f;
    #pragma unroll 8
    for (int k = 0; k < K; k++){
        float w = W[(size_t)k*N + n];
        const float4* xp = (const float4*)(Xs + k*16);
        float4 x0 = xp[0], x1 = xp[1], x2 = xp[2], x3 = xp[3];
        acc[0]+=x0.x*w; acc[1]+=x0.y*w; acc[2]+=x0.z*w; acc[3]+=x0.w*w;
        acc[4]+=x1.x*w; acc[5]+=x1.y*w; acc[6]+=x1.z*w; acc[7]+=x1.w*w;
        acc[8]+=x2.x*w; acc[9]+=x2.y*w; acc[10]+=x2.z*w; acc[11]+=x2.w*w;
        acc[12]+=x3.x*w; acc[13]+=x3.y*w; acc[14]+=x3.z*w; acc[15]+=x3.w*w;
    }
    float bv = bias[n];
    #pragma unroll
    for (int b = 0; b < 16; b++) Y[(size_t)b*N + n] = acc[b] + bv;
}

// ---------------- transpose dynamic weights: p -> pt ----------------
__global__ void k_prep(const float* __restrict__ p, float* __restrict__ pt){
    __shared__ float t[32][33];
    int b = blockIdx.z, mat = blockIdx.y;
    int cols = (mat == 2) ? 64 : FIN;
    int ntx = cols / 32;
    int ntiles = 2 * ntx;
    int tile = blockIdx.x;
    if (tile >= ntiles) return;
    int tf = tile / ntx, ti = tile % ntx;
    int srcoff = (mat == 0) ? OFF_KIN : (mat == 1) ? OFF_KSK : OFF_KOUT;
    int dstoff = (mat == 0) ? 0 : (mat == 1) ? 36864 : 73728;
    const float* src = p + (size_t)b*PD + srcoff;
    float* dst = pt + (size_t)b*PTS + dstoff;
    int f0 = tf*32, i0 = ti*32;
    for (int r = threadIdx.y; r < 32; r += 8)
        t[r][threadIdx.x] = src[(f0+r)*cols + i0 + threadIdx.x];
    __syncthreads();
    for (int r = threadIdx.y; r < 32; r += 8)
        dst[(i0+r)*64 + f0 + threadIdx.x] = t[threadIdx.x][r];
}

// ---------------- perceive (dilated Sobel bank) + instance norm ----------------
__global__ void __launch_bounds__(256) k_perceive(const float* __restrict__ out,
                                                  float* __restrict__ feat){
    __shared__ float xs[64*64];
    __shared__ float rs1[8], rs2[8], bcast[2];
    int bcid = blockIdx.x;
    int b = bcid >> 6, c = bcid & 63;
    const float* src = out + (size_t)bcid*HWD;
    for (int p = threadIdx.x; p < HWD; p += 256) xs[p] = src[p];
    __syncthreads();
    int lane = threadIdx.x & 31, wrp = threadIdx.x >> 5;
    for (int g = 0; g < 9; g++){
        float v[16];
        float s1 = 0.f, s2 = 0.f;
        int d = (g == 0) ? 0 : (1 << ((g-1) >> 1));
        int isX = ((g-1) & 1) == 0;
        #pragma unroll
        for (int t = 0; t < 16; t++){
            int p = threadIdx.x + t*256;
            int i = p >> 6, j = p & 63;
            float val;
            if (g == 0){
                val = xs[p];
            } else {
                int im = i-d, ip = i+d, jm = j-d, jp = j+d;
                bool imv = im >= 0, ipv = ip < 64, jmv = jm >= 0, jpv = jp < 64;
                if (isX){
                    float t0 = ((imv&&jpv) ? xs[im*64+jp] : 0.f) - ((imv&&jmv) ? xs[im*64+jm] : 0.f);
                    float t1 = (jpv ? xs[i*64+jp] : 0.f)         - (jmv ? xs[i*64+jm] : 0.f);
                    float t2 = ((ipv&&jpv) ? xs[ip*64+jp] : 0.f) - ((ipv&&jmv) ? xs[ip*64+jm] : 0.f);
                    val = 0.125f*(t0 + 2.f*t1 + t2);
                } else {
                    float t0 = ((ipv&&jmv) ? xs[ip*64+jm] : 0.f) - ((imv&&jmv) ? xs[im*64+jm] : 0.f);
                    float t1 = (ipv ? xs[ip*64+j] : 0.f)         - (imv ? xs[im*64+j] : 0.f);
                    float t2 = ((ipv&&jpv) ? xs[ip*64+jp] : 0.f) - ((imv&&jpv) ? xs[im*64+jp] : 0.f);
                    val = 0.125f*(t0 + 2.f*t1 + t2);
                }
            }
            v[t] = val; s1 += val; s2 += val*val;
        }
        #pragma unroll
        for (int s = 16; s > 0; s >>= 1){
            s1 += __shfl_xor_sync(0xffffffffu, s1, s);
            s2 += __shfl_xor_sync(0xffffffffu, s2, s);
        }
        if (lane == 0){ rs1[wrp] = s1; rs2[wrp] = s2; }
        __syncthreads();
        if (threadIdx.x == 0){
            float a = 0.f, q = 0.f;
            #pragma unroll
            for (int w = 0; w < 8; w++){ a += rs1[w]; q += rs2[w]; }
            float mean = a*(1.f/4096.f);
            float var  = q*(1.f/4096.f) - mean*mean;
            bcast[0] = mean; bcast[1] = rsqrtf(var + 1e-5f);
        }
        __syncthreads();
        float mean = bcast[0], inv = bcast[1];
        float* dst = feat + ((size_t)b*FIN + g*64 + c)*HWD;
        #pragma unroll
        for (int t = 0; t < 16; t++)
            dst[threadIdx.x + t*256] = (v[t]-mean)*inv;
    }
}

// ---------------- dyn-conv GEMMs: M=64, Ntile=256, Kchunk=32, 8x8/thread ----------------
// smem: As2 = A dup-packed [DKC][128] (16KB), Bs [DKC][256] (32KB) -> 48KB
__device__ __forceinline__ void fill_tiles(const float* __restrict__ Bsrc,
                                           const float* __restrict__ Asrc,
                                           float* Bs, float* As2, int tid){
    #pragma unroll
    for (int q = 0; q < 8; q++){          // 32*256/4 = 2048 float4 / 256 thr
        int fid = q*256 + tid;
        int row = fid >> 6, c4 = fid & 63;
        float4 v = *(const float4*)(Bsrc + (size_t)row*HWD + c4*4);
        *(float4*)(Bs + row*DTN + c4*4) = v;
    }
    #pragma unroll
    for (int q = 0; q < 2; q++){          // 32*64/4 = 512 float4 / 256 thr
        int fid = q*256 + tid;
        int row = fid >> 4, c4 = fid & 15;
        float4 v = *(const float4*)(Asrc + row*64 + c4*4);
        ull* d = (ull*)(As2 + row*128 + c4*8);
        d[0] = dup2(v.x); d[1] = dup2(v.y); d[2] = dup2(v.z); d[3] = dup2(v.w);
    }
}

__device__ __forceinline__ void mma_chunk(const float* Bs, const float* As2,
                                          ull acc[8][4], int tm, int tn){
    #pragma unroll 4
    for (int k = 0; k < DKC; k++){
        ull b0 = *(const ull*)(Bs + k*DTN +       2*tn);
        ull b1 = *(const ull*)(Bs + k*DTN +  64 + 2*tn);
        ull b2 = *(const ull*)(Bs + k*DTN + 128 + 2*tn);
        ull b3 = *(const ull*)(Bs + k*DTN + 192 + 2*tn);
        #pragma unroll
        for (int r = 0; r < 8; r++){
            ull a = *(const ull*)(As2 + k*128 + 2*(tm*8 + r));
            ffma2(acc[r][0], a, b0); ffma2(acc[r][1], a, b1);
            ffma2(acc[r][2], a, b2); ffma2(acc[r][3], a, b3);
        }
    }
}

__global__ void __launch_bounds__(256, 2) k_dynH(
    const float* __restrict__ pt, const float* __restrict__ p,
    const float* __restrict__ feat, float* __restrict__ h)
{
    extern __shared__ float sm[];
    float* As2 = sm;                 // 32*128 = 4096 floats
    float* Bs  = sm + DKC*128;       // 32*256 = 8192 floats
    int b = blockIdx.y, n0 = blockIdx.x*DTN;
    int tid = threadIdx.x, tm = tid >> 5, tn = tid & 31;
    const float* featb = feat + (size_t)b*FIN*HWD + n0;
    const float* kinT  = pt + (size_t)b*PTS;
    const float* pb    = p + (size_t)b*PD;

    ull acc[8][4];
    #pragma unroll
    for (int r = 0; r < 8; r++){ acc[r][0]=0; acc[r][1]=0; acc[r][2]=0; acc[r][3]=0; }

    for (int k0 = 0; k0 < FIN; k0 += DKC){
        __syncthreads();
        fill_tiles(featb + (size_t)k0*HWD, kinT + k0*64, Bs, As2, tid);
        __syncthreads();
        mma_chunk(Bs, As2, acc, tm, tn);
    }
    #pragma unroll
    for (int r = 0; r < 8; r++){
        int m = tm*8 + r;
        float bi = pb[OFF_BIN + m];
        float* dst = h + ((size_t)(b*NF + m))*HWD + n0;
        #pragma unroll
        for (int j = 0; j < 4; j++){
            float lo, hi; unpack2(acc[r][j], lo, hi);
            *(ull*)(dst + j*64 + 2*tn) = pack2(lrelu(lo+bi), lrelu(hi+bi));
        }
    }
}

__global__ void __launch_bounds__(256, 2) k_dynO(
    const float* __restrict__ pt, const float* __restrict__ p,
    const float* __restrict__ feat, const float* __restrict__ h,
    float* __restrict__ outp)
{
    extern __shared__ float sm[];
    float* As2 = sm;
    float* Bs  = sm + DKC*128;
    int b = blockIdx.y, n0 = blockIdx.x*DTN;
    int tid = threadIdx.x, tm = tid >> 5, tn = tid & 31;
    const float* featb = feat + (size_t)b*FIN*HWD + n0;
    const float* hb    = h + (size_t)b*NF*HWD + n0;
    const float* kskT  = pt + (size_t)b*PTS + 36864;
    const float* koutT = pt + (size_t)b*PTS + 73728;
    const float* pb    = p + (size_t)b*PD;

    ull acc[8][4];
    #pragma unroll
    for (int r = 0; r < 8; r++){ acc[r][0]=0; acc[r][1]=0; acc[r][2]=0; acc[r][3]=0; }

    for (int k0 = 0; k0 < FIN; k0 += DKC){
        __syncthreads();
        fill_tiles(featb + (size_t)k0*HWD, kskT + k0*64, Bs, As2, tid);
        __syncthreads();
        mma_chunk(Bs, As2, acc, tm, tn);
    }
    for (int k0 = 0; k0 < 64; k0 += DKC){
        __syncthreads();
        fill_tiles(hb + (size_t)k0*HWD, koutT + k0*64, Bs, As2, tid);
        __syncthreads();
        mma_chunk(Bs, As2, acc, tm, tn);
    }
    #pragma unroll
    for (int r = 0; r < 8; r++){
        int m = tm*8 + r;
        float bi = pb[OFF_BOUT + m] + pb[OFF_BSK + m];
        float* dst = outp + ((size_t)(b*NF + m))*HWD + n0;
        #pragma unroll
        for (int j = 0; j < 4; j++){
            float lo, hi; unpack2(acc[r][j], lo, hi);
            *(ull*)(dst + j*64 + 2*tn) = pack2(lo+bi, hi+bi);
        }
    }
}

// ---------------- freq = (out . pe) / 4096 into cat[:, 512:] ----------------
__global__ void __launch_bounds__(128) k_freq(const float* __restrict__ out,
                                              const float* __restrict__ pe,
                                              float* __restrict__ cat){
    int b = blockIdx.y;
    int c0 = blockIdx.x*4;
    const float* o0 = out + ((size_t)b*NF + c0)*HWD;
    float acc[4][24];
    #pragma unroll
    for (int ch = 0; ch < 4; ch++)
        #pragma unroll
        for (int f = 0; f < 24; f++) acc[ch][f] = 0.f;
    for (int p = threadIdx.x; p < HWD; p += 128){
        float ov0 = o0[p], ov1 = o0[HWD+p], ov2 = o0[2*HWD+p], ov3 = o0[3*HWD+p];
        #pragma unroll
        for (int f = 0; f < 24; f++){
            float pv = pe[f*HWD + p];
            acc[0][f] += ov0*pv; acc[1][f] += ov1*pv;
            acc[2][f] += ov2*pv; acc[3][f] += ov3*pv;
        }
    }
    __shared__ float red[4][4][24];
    int lane = threadIdx.x & 31, wrp = threadIdx.x >> 5;
    #pragma unroll
    for (int ch = 0; ch < 4; ch++)
        #pragma unroll
        for (int f = 0; f < 24; f++){
            float v = acc[ch][f];
            #pragma unroll
            for (int s = 16; s > 0; s >>= 1) v += __shfl_xor_sync(0xffffffffu, v, s);
            if (lane == 0) red[wrp][ch][f] = v;
        }
    __syncthreads();
    if (threadIdx.x < 96){
        int ch = threadIdx.x / 24, f = threadIdx.x % 24;
        float s = red[0][ch][f] + red[1][ch][f] + red[2][ch][f] + red[3][ch][f];
        cat[b*CATD + 512 + (c0+ch)*24 + f] = s * (1.f/4096.f);
    }
}

// ---------------- host orchestration ----------------
extern "C" void kernel_launch(void* const* d_in, const int* in_sizes, int n_in,
                              void* d_out, int out_size){
    const float* x      = (const float*)d_in[0];
    const float* inj    = (const float*)d_in[1];
    const float* w_in   = (const float*)d_in[2];
    const float* b_in   = (const float*)d_in[3];
    const float* fl_w1  = (const float*)d_in[4];
    const float* fl_b1  = (const float*)d_in[5];
    const float* fl_w2  = (const float*)d_in[6];
    const float* fl_b2  = (const float*)d_in[7];
    const float* fl_ws  = (const float*)d_in[8];
    const float* fl_bs  = (const float*)d_in[9];
    const float* dyn_w  = (const float*)d_in[10];
    const float* dyn_b  = (const float*)d_in[11];
    const float* pe     = (const float*)d_in[12];
    const float* otl_w1 = (const float*)d_in[13];
    const float* otl_b1 = (const float*)d_in[14];
    const float* otl_w2 = (const float*)d_in[15];
    const float* otl_b2 = (const float*)d_in[16];
    const float* otl_ws = (const float*)d_in[17];
    const float* otl_bs = (const float*)d_in[18];
    const float* ltl_w  = (const float*)d_in[19];
    const float* ltl_b  = (const float*)d_in[20];

    float *p_out, *p_feat, *p_h, *p_p, *p_pt, *p_injA, *p_injB, *p_latA, *p_latB;
    float *p_t512, *p_cat, *p_t2048, *p_part;
    cudaGetSymbolAddress((void**)&p_out,  g_out);
    cudaGetSymbolAddress((void**)&p_feat, g_feat);
    cudaGetSymbolAddress((void**)&p_h,    g_h);
    cudaGetSymbolAddress((void**)&p_p,    g_p);
    cudaGetSymbolAddress((void**)&p_pt,   g_pt);
    cudaGetSymbolAddress((void**)&p_injA, g_injA);
    cudaGetSymbolAddress((void**)&p_injB, g_injB);
    cudaGetSymbolAddress((void**)&p_latA, g_latA);
    cudaGetSymbolAddress((void**)&p_latB, g_latB);
    cudaGetSymbolAddress((void**)&p_t512, g_t512);
    cudaGetSymbolAddress((void**)&p_cat,  g_cat);
    cudaGetSymbolAddress((void**)&p_t2048,g_t2048);
    cudaGetSymbolAddress((void**)&p_part, g_part);

    static int smem_set = 0;
    if (!smem_set){
        cudaFuncSetAttribute(k_dynH, cudaFuncAttributeMaxDynamicSharedMemorySize, 49152);
        cudaFuncSetAttribute(k_dynO, cudaFuncAttributeMaxDynamicSharedMemorySize, 49152);
        smem_set = 1;
    }

    cudaMemcpyAsync(p_injA, inj, (size_t)NB*LATD*sizeof(float), cudaMemcpyDeviceToDevice);
    k_zero<<<16, 512>>>(p_latA);
    k_init_out<<<NB*NF, 256>>>(x, w_in, b_in, p_out);

    float* injC = p_injA; float* injN = p_injB;
    float* latC = p_latA; float* latN = p_latB;

    for (int c = 0; c < 4; c++){
        // feat = inorm(perceive(out)) — independent of the latent chain; run first
        k_perceive<<<NB*NF, 256>>>(p_out, p_feat);

        // inj_lat = lin_res(inj_lat, fl_*)
        gemm16_part<<<dim3(4,8), 128>>>(injC, LATD, fl_w1, p_part, LATD, 64, 0);
        gemm16_reduce<<<32, 256>>>(p_part, 8, fl_b1, nullptr, p_t512, LATD, 1);
        gemm16_part<<<dim3(4,8), 128>>>(injC, LATD, fl_ws, p_part, LATD, 64, 0);
        gemm16_part<<<dim3(4,8), 128>>>(p_t512, LATD, fl_w2, p_part, LATD, 64, 8);
        gemm16_reduce<<<32, 256>>>(p_part, 16, fl_bs, fl_b2, injN, LATD, 0);

        // p = inj_lat @ dyn_w + dyn_b; transpose dynamic kernels
        gemm16_full<<<(PD + 127)/128, 128>>>(injN, LATD, dyn_w, dyn_b, p_p, PD);
        k_prep<<<dim3(36, 3, NB), dim3(32, 8)>>>(p_p, p_pt);

        // dynamic conv: h then out
        k_dynH<<<dim3(HWD/DTN, NB), 256, 49152>>>(p_pt, p_p, p_feat, p_h);
        k_dynO<<<dim3(HWD/DTN, NB), 256, 49152>>>(p_pt, p_p, p_feat, p_h, p_out);

        // cat = [lat, freq]
        k_freq<<<dim3(16, NB), 128>>>(p_out, pe, p_cat);
        k_copylat<<<32, 256>>>(latC, p_cat);

        // lat = lin_res(cat, otl_*[c])
        const float* w1 = otl_w1 + (size_t)c*CATD*CATD;
        const float* b1 = otl_b1 + (size_t)c*CATD;
        const float* w2 = otl_w2 + (size_t)c*CATD*LATD;
        const float* b2 = otl_b2 + (size_t)c*LATD;
        const float* ws = otl_ws + (size_t)c*CATD*LATD;
        const float* bs = otl_bs + (size_t)c*LATD;
        gemm16_part<<<dim3(16,8), 128>>>(p_cat, CATD, w1, p_part, CATD, 256, 0);
        gemm16_reduce<<<128, 256>>>(p_part, 8, b1, nullptr, p_t2048, CATD, 1);
        gemm16_part<<<dim3(4,8), 128>>>(p_cat, CATD, ws, p_part, LATD, 256, 0);
        gemm16_part<<<dim3(4,8), 128>>>(p_t2048, CATD, w2, p_part, LATD, 256, 8);
        gemm16_reduce<<<32, 256>>>(p_part, 16, bs, b2, latN, LATD, 0);

        float* t;
        t = injC; injC = injN; injN = t;
        t = latC; latC = latN; latN = t;
    }

    // out = lat @ ltl_w + ltl_b
    gemm16_part<<<dim3(4,8), 128>>>(latC, LATD, ltl_w, p_part, LATD, 64, 0);
    gemm16_reduce<<<32, 256>>>(p_part, 8, ltl_b, nullptr, (float*)d_out, LATD, 0);
}

// round 10
// speedup vs baseline: 1.4161x; 1.3840x over previous
#include <cuda_runtime.h>

#define NB   16
#define NF   64
#define LATD 512
#define IMG  64
#define HWD  4096
#define FIN  576
#define PD   78016
#define CATD 2048

#define OFF_KIN  0
#define OFF_BIN  36864
#define OFF_KOUT 36928
#define OFF_BOUT 41024
#define OFF_KSK  41088
#define OFF_BSK  77952

#define PTS  77824
#define DTN  256
#define DKC  32

#define LDW  (16*LATD)    // slot stride, weight-stream partials
#define LDM  (16*CATD)    // slot stride, main/otl partials

typedef unsigned long long ull;

// ---------------- scratch ----------------
__device__ float g_out [2][NB*NF*HWD];
__device__ float g_feat[(size_t)NB*FIN*HWD];
__device__ float g_h   [NB*NF*HWD];
__device__ float g_p   [4][NB*PD];
__device__ float g_pt  [4][NB*PTS];
__device__ float g_injA[NB*LATD], g_injB[NB*LATD];
__device__ float g_latA[NB*LATD], g_latB[NB*LATD];
__device__ float g_cat [NB*CATD];
__device__ float g_partW[24*LDW];
__device__ float g_partM[24*LDM];

__device__ __forceinline__ float lrelu(float v){ return v > 0.f ? v : 0.2f*v; }
__device__ __forceinline__ void ffma2(ull& d, ull a, ull b){
    asm("fma.rn.f32x2 %0, %1, %2, %0;" : "+l"(d) : "l"(a), "l"(b));
}
__device__ __forceinline__ ull dup2(float v){
    ull r; asm("mov.b64 %0, {%1, %1};" : "=l"(r) : "f"(v)); return r;
}
__device__ __forceinline__ ull pack2(float lo, float hi){
    ull r; asm("mov.b64 %0, {%1, %2};" : "=l"(r) : "f"(lo), "f"(hi)); return r;
}
__device__ __forceinline__ void unpack2(ull v, float& lo, float& hi){
    asm("mov.b64 {%0, %1}, %2;" : "=f"(lo), "=f"(hi) : "l"(v));
}

// ---------------- init ----------------
__global__ void k_init_out(const float* __restrict__ x, const float* __restrict__ w_in,
                           const float* __restrict__ b_in, float* __restrict__ out){
    int b = blockIdx.x >> 6, o = blockIdx.x & 63;
    float w0 = w_in[o*3+0], w1 = w_in[o*3+1], w2 = w_in[o*3+2], bb = b_in[o];
    const float* xb = x + (size_t)b*3*HWD;
    float* ob = out + (size_t)blockIdx.x*HWD;
    for (int p = threadIdx.x; p < HWD; p += blockDim.x)
        ob[p] = w0*xb[p] + w1*xb[HWD+p] + w2*xb[2*HWD+p] + bb;
}
__global__ void k_zero(float* p){ p[blockIdx.x*512 + threadIdx.x] = 0.f; }
__global__ void k_copylat(const float* __restrict__ lat, float* __restrict__ cat){
    int idx = blockIdx.x*256 + threadIdx.x;
    int b = idx >> 9, n = idx & 511;
    cat[b*CATD + n] = lat[idx];
}

// ---------------- small GEMM family: Y(16,N) = X(16,K) @ W(K,N) ----------------
__global__ void __launch_bounds__(128) gemm16_part(
    const float* __restrict__ X, int K, const float* __restrict__ W,
    float* __restrict__ Yp, int N, int kc, int slot0, int ldslot)
{
    __shared__ __align__(16) float Xs[256*16];
    int ks = blockIdx.y, k0 = ks*kc;
    int klen = min(kc, K - k0);
    for (int k = threadIdx.x; k < klen; k += 128){
        #pragma unroll
        for (int b = 0; b < 16; b++) Xs[k*16+b] = X[(size_t)b*K + k0 + k];
    }
    __syncthreads();
    int n = blockIdx.x*128 + threadIdx.x;
    if (n >= N) return;
    float acc[16];
    #pragma unroll
    for (int b = 0; b < 16; b++) acc[b] = 0.f;
    #pragma unroll 4
    for (int k = 0; k < klen; k++){
        float w = W[(size_t)(k0+k)*N + n];
        const float4* xp = (const float4*)(Xs + k*16);
        float4 x0 = xp[0], x1 = xp[1], x2 = xp[2], x3 = xp[3];
        acc[0]+=x0.x*w; acc[1]+=x0.y*w; acc[2]+=x0.z*w; acc[3]+=x0.w*w;
        acc[4]+=x1.x*w; acc[5]+=x1.y*w; acc[6]+=x1.z*w; acc[7]+=x1.w*w;
        acc[8]+=x2.x*w; acc[9]+=x2.y*w; acc[10]+=x2.z*w; acc[11]+=x2.w*w;
        acc[12]+=x3.x*w; acc[13]+=x3.y*w; acc[14]+=x3.z*w; acc[15]+=x3.w*w;
    }
    float* yp = Yp + (size_t)(slot0+ks)*ldslot;
    #pragma unroll
    for (int b = 0; b < 16; b++) yp[(size_t)b*N + n] = acc[b];
}

// X_eff[b][k] = lrelu(b1[k] + sum_s Ypin[s][b][k]); partials of X_eff @ W
__global__ void __launch_bounds__(128) gemm16_part_red(
    const float* __restrict__ Ypin, int Kin, int nsl, const float* __restrict__ b1,
    const float* __restrict__ W, float* __restrict__ Yp, int N, int kc,
    int slot0, int ldin, int ldout)
{
    __shared__ __align__(16) float Xs[256*16];
    int ks = blockIdx.y, k0 = ks*kc;
    int klen = min(kc, Kin - k0);
    for (int k = threadIdx.x; k < klen; k += 128){
        float bv = b1[k0 + k];
        #pragma unroll
        for (int b = 0; b < 16; b++){
            float s = bv;
            for (int t = 0; t < nsl; t++)
                s += Ypin[(size_t)t*ldin + (size_t)b*Kin + k0 + k];
            Xs[k*16+b] = lrelu(s);
        }
    }
    __syncthreads();
    int n = blockIdx.x*128 + threadIdx.x;
    if (n >= N) return;
    float acc[16];
    #pragma unroll
    for (int b = 0; b < 16; b++) acc[b] = 0.f;
    #pragma unroll 4
    for (int k = 0; k < klen; k++){
        float w = W[(size_t)(k0+k)*N + n];
        const float4* xp = (const float4*)(Xs + k*16);
        float4 x0 = xp[0], x1 = xp[1], x2 = xp[2], x3 = xp[3];
        acc[0]+=x0.x*w; acc[1]+=x0.y*w; acc[2]+=x0.z*w; acc[3]+=x0.w*w;
        acc[4]+=x1.x*w; acc[5]+=x1.y*w; acc[6]+=x1.z*w; acc[7]+=x1.w*w;
        acc[8]+=x2.x*w; acc[9]+=x2.y*w; acc[10]+=x2.z*w; acc[11]+=x2.w*w;
        acc[12]+=x3.x*w; acc[13]+=x3.y*w; acc[14]+=x3.z*w; acc[15]+=x3.w*w;
    }
    float* yp = Yp + (size_t)(slot0+ks)*ldout;
    #pragma unroll
    for (int b = 0; b < 16; b++) yp[(size_t)b*N + n] = acc[b];
}

__global__ void gemm16_reduce_fin(const float* __restrict__ Yp, int s0, int cnt,
                                  const float* __restrict__ b1, const float* __restrict__ b2,
                                  float* __restrict__ Y, int N, int ldslot)
{
    int idx = blockIdx.x*256 + threadIdx.x;
    if (idx >= 16*N) return;
    int n = idx % N, b = idx / N;
    float s = 0.f;
    for (int t = 0; t < cnt; t++) s += Yp[(size_t)(s0+t)*ldslot + (size_t)b*N + n];
    if (b1) s += b1[n];
    if (b2) s += b2[n];
    Y[idx] = s;
}

__global__ void __launch_bounds__(128) gemm16_full(
    const float* __restrict__ X, int K, const float* __restrict__ W,
    const float* __restrict__ bias, float* __restrict__ Y, int N)
{
    __shared__ __align__(16) float Xs[512*16];
    for (int k = threadIdx.x; k < K; k += 128){
        #pragma unroll
        for (int b = 0; b < 16; b++) Xs[k*16+b] = X[(size_t)b*K + k];
    }
    __syncthreads();
    int n = blockIdx.x*128 + threadIdx.x;
    if (n >= N) return;
    float acc[16];
    #pragma unroll
    for (int b = 0; b < 16; b++) acc[b] = 0.f;
    #pragma unroll 8
    for (int k = 0; k < K; k++){
        float w = W[(size_t)k*N + n];
        const float4* xp = (const float4*)(Xs + k*16);
        float4 x0 = xp[0], x1 = xp[1], x2 = xp[2], x3 = xp[3];
        acc[0]+=x0.x*w; acc[1]+=x0.y*w; acc[2]+=x0.z*w; acc[3]+=x0.w*w;
        acc[4]+=x1.x*w; acc[5]+=x1.y*w; acc[6]+=x1.z*w; acc[7]+=x1.w*w;
        acc[8]+=x2.x*w; acc[9]+=x2.y*w; acc[10]+=x2.z*w; acc[11]+=x2.w*w;
        acc[12]+=x3.x*w; acc[13]+=x3.y*w; acc[14]+=x3.z*w; acc[15]+=x3.w*w;
    }
    float bv = bias[n];
    #pragma unroll
    for (int b = 0; b < 16; b++) Y[(size_t)b*N + n] = acc[b] + bv;
}

// ---------------- transpose dynamic weights ----------------
__global__ void k_prep(const float* __restrict__ p, float* __restrict__ pt){
    __shared__ float t[32][33];
    int b = blockIdx.z, mat = blockIdx.y;
    int cols = (mat == 2) ? 64 : FIN;
    int ntx = cols / 32;
    int ntiles = 2 * ntx;
    int tile = blockIdx.x;
    if (tile >= ntiles) return;
    int tf = tile / ntx, ti = tile % ntx;
    int srcoff = (mat == 0) ? OFF_KIN : (mat == 1) ? OFF_KSK : OFF_KOUT;
    int dstoff = (mat == 0) ? 0 : (mat == 1) ? 36864 : 73728;
    const float* src = p + (size_t)b*PD + srcoff;
    float* dst = pt + (size_t)b*PTS + dstoff;
    int f0 = tf*32, i0 = ti*32;
    for (int r = threadIdx.y; r < 32; r += 8)
        t[r][threadIdx.x] = src[(f0+r)*cols + i0 + threadIdx.x];
    __syncthreads();
    for (int r = threadIdx.y; r < 32; r += 8)
        dst[(i0+r)*64 + f0 + threadIdx.x] = t[threadIdx.x][r];
}

// ---------------- perceive + inorm, split 3 ways over groups ----------------
__global__ void __launch_bounds__(256) k_perceive(const float* __restrict__ out,
                                                  float* __restrict__ feat){
    __shared__ float xs[64*64];
    __shared__ float rs1[8], rs2[8], bcast[2];
    int bcid = blockIdx.x, gs = blockIdx.y;
    int b = bcid >> 6, c = bcid & 63;
    const float* src = out + (size_t)bcid*HWD;
    for (int p = threadIdx.x; p < HWD; p += 256) xs[p] = src[p];
    __syncthreads();
    int lane = threadIdx.x & 31, wrp = threadIdx.x >> 5;
    for (int g = gs*3; g < gs*3+3; g++){
        float v[16];
        float s1 = 0.f, s2 = 0.f;
        int d = (g == 0) ? 0 : (1 << ((g-1) >> 1));
        int isX = ((g-1) & 1) == 0;
        #pragma unroll
        for (int t = 0; t < 16; t++){
            int p = threadIdx.x + t*256;
            int i = p >> 6, j = p & 63;
            float val;
            if (g == 0){
                val = xs[p];
            } else {
                int im = i-d, ip = i+d, jm = j-d, jp = j+d;
                bool imv = im >= 0, ipv = ip < 64, jmv = jm >= 0, jpv = jp < 64;
                if (isX){
                    float t0 = ((imv&&jpv) ? xs[im*64+jp] : 0.f) - ((imv&&jmv) ? xs[im*64+jm] : 0.f);
                    float t1 = (jpv ? xs[i*64+jp] : 0.f)         - (jmv ? xs[i*64+jm] : 0.f);
                    float t2 = ((ipv&&jpv) ? xs[ip*64+jp] : 0.f) - ((ipv&&jmv) ? xs[ip*64+jm] : 0.f);
                    val = 0.125f*(t0 + 2.f*t1 + t2);
                } else {
                    float t0 = ((ipv&&jmv) ? xs[ip*64+jm] : 0.f) - ((imv&&jmv) ? xs[im*64+jm] : 0.f);
                    float t1 = (ipv ? xs[ip*64+j] : 0.f)         - (imv ? xs[im*64+j] : 0.f);
                    float t2 = ((ipv&&jpv) ? xs[ip*64+jp] : 0.f) - ((imv&&jpv) ? xs[im*64+jp] : 0.f);
                    val = 0.125f*(t0 + 2.f*t1 + t2);
                }
            }
            v[t] = val; s1 += val; s2 += val*val;
        }
        #pragma unroll
        for (int s = 16; s > 0; s >>= 1){
            s1 += __shfl_xor_sync(0xffffffffu, s1, s);
            s2 += __shfl_xor_sync(0xffffffffu, s2, s);
        }
        if (lane == 0){ rs1[wrp] = s1; rs2[wrp] = s2; }
        __syncthreads();
        if (threadIdx.x == 0){
            float a = 0.f, q = 0.f;
            #pragma unroll
            for (int w = 0; w < 8; w++){ a += rs1[w]; q += rs2[w]; }
            float mean = a*(1.f/4096.f);
            float var  = q*(1.f/4096.f) - mean*mean;
            bcast[0] = mean; bcast[1] = rsqrtf(var + 1e-5f);
        }
        __syncthreads();
        float mean = bcast[0], inv = bcast[1];
        float* dst = feat + ((size_t)b*FIN + g*64 + c)*HWD;
        #pragma unroll
        for (int t = 0; t < 16; t++)
            dst[threadIdx.x + t*256] = (v[t]-mean)*inv;
        __syncthreads();
    }
}

// ---------------- dyn-conv GEMMs (R8 best version) ----------------
__device__ __forceinline__ void fill_tiles(const float* __restrict__ Bsrc,
                                           const float* __restrict__ Asrc,
                                           float* Bs, float* As2, int tid){
    #pragma unroll
    for (int q = 0; q < 8; q++){
        int fid = q*256 + tid;
        int row = fid >> 6, c4 = fid & 63;
        float4 v = *(const float4*)(Bsrc + (size_t)row*HWD + c4*4);
        *(float4*)(Bs + row*DTN + c4*4) = v;
    }
    #pragma unroll
    for (int q = 0; q < 2; q++){
        int fid = q*256 + tid;
        int row = fid >> 4, c4 = fid & 15;
        float4 v = *(const float4*)(Asrc + row*64 + c4*4);
        ull* d = (ull*)(As2 + row*128 + c4*8);
        d[0] = dup2(v.x); d[1] = dup2(v.y); d[2] = dup2(v.z); d[3] = dup2(v.w);
    }
}
__device__ __forceinline__ void mma_chunk(const float* Bs, const float* As2,
                                          ull acc[8][4], int tm, int tn){
    #pragma unroll 4
    for (int k = 0; k < DKC; k++){
        ull b0 = *(const ull*)(Bs + k*DTN +       2*tn);
        ull b1 = *(const ull*)(Bs + k*DTN +  64 + 2*tn);
        ull b2 = *(const ull*)(Bs + k*DTN + 128 + 2*tn);
        ull b3 = *(const ull*)(Bs + k*DTN + 192 + 2*tn);
        #pragma unroll
        for (int r = 0; r < 8; r++){
            ull a = *(const ull*)(As2 + k*128 + 2*(tm*8 + r));
            ffma2(acc[r][0], a, b0); ffma2(acc[r][1], a, b1);
            ffma2(acc[r][2], a, b2); ffma2(acc[r][3], a, b3);
        }
    }
}

__global__ void __launch_bounds__(256, 2) k_dynH(
    const float* __restrict__ pt, const float* __restrict__ p,
    const float* __restrict__ feat, float* __restrict__ h)
{
    extern __shared__ float sm[];
    float* As2 = sm;
    float* Bs  = sm + DKC*128;
    int b = blockIdx.y, n0 = blockIdx.x*DTN;
    int tid = threadIdx.x, tm = tid >> 5, tn = tid & 31;
    const float* featb = feat + (size_t)b*FIN*HWD + n0;
    const float* kinT  = pt + (size_t)b*PTS;
    const float* pb    = p + (size_t)b*PD;
    ull acc[8][4];
    #pragma unroll
    for (int r = 0; r < 8; r++){ acc[r][0]=0; acc[r][1]=0; acc[r][2]=0; acc[r][3]=0; }
    for (int k0 = 0; k0 < FIN; k0 += DKC){
        __syncthreads();
        fill_tiles(featb + (size_t)k0*HWD, kinT + k0*64, Bs, As2, tid);
        __syncthreads();
        mma_chunk(Bs, As2, acc, tm, tn);
    }
    #pragma unroll
    for (int r = 0; r < 8; r++){
        int m = tm*8 + r;
        float bi = pb[OFF_BIN + m];
        float* dst = h + ((size_t)(b*NF + m))*HWD + n0;
        #pragma unroll
        for (int j = 0; j < 4; j++){
            float lo, hi; unpack2(acc[r][j], lo, hi);
            *(ull*)(dst + j*64 + 2*tn) = pack2(lrelu(lo+bi), lrelu(hi+bi));
        }
    }
}

__global__ void __launch_bounds__(256, 2) k_dynO(
    const float* __restrict__ pt, const float* __restrict__ p,
    const float* __restrict__ feat, const float* __restrict__ h,
    float* __restrict__ outp)
{
    extern __shared__ float sm[];
    float* As2 = sm;
    float* Bs  = sm + DKC*128;
    int b = blockIdx.y, n0 = blockIdx.x*DTN;
    int tid = threadIdx.x, tm = tid >> 5, tn = tid & 31;
    const float* featb = feat + (size_t)b*FIN*HWD + n0;
    const float* hb    = h + (size_t)b*NF*HWD + n0;
    const float* kskT  = pt + (size_t)b*PTS + 36864;
    const float* koutT = pt + (size_t)b*PTS + 73728;
    const float* pb    = p + (size_t)b*PD;
    ull acc[8][4];
    #pragma unroll
    for (int r = 0; r < 8; r++){ acc[r][0]=0; acc[r][1]=0; acc[r][2]=0; acc[r][3]=0; }
    for (int k0 = 0; k0 < FIN; k0 += DKC){
        __syncthreads();
        fill_tiles(featb + (size_t)k0*HWD, kskT + k0*64, Bs, As2, tid);
        __syncthreads();
        mma_chunk(Bs, As2, acc, tm, tn);
    }
    for (int k0 = 0; k0 < 64; k0 += DKC){
        __syncthreads();
        fill_tiles(hb + (size_t)k0*HWD, koutT + k0*64, Bs, As2, tid);
        __syncthreads();
        mma_chunk(Bs, As2, acc, tm, tn);
    }
    #pragma unroll
    for (int r = 0; r < 8; r++){
        int m = tm*8 + r;
        float bi = pb[OFF_BOUT + m] + pb[OFF_BSK + m];
        float* dst = outp + ((size_t)(b*NF + m))*HWD + n0;
        #pragma unroll
        for (int j = 0; j < 4; j++){
            float lo, hi; unpack2(acc[r][j], lo, hi);
            *(ull*)(dst + j*64 + 2*tn) = pack2(lo+bi, hi+bi);
        }
    }
}

// ---------------- freq ----------------
__global__ void __launch_bounds__(128) k_freq(const float* __restrict__ out,
                                              const float* __restrict__ pe,
                                              float* __restrict__ cat){
    int b = blockIdx.y;
    int c0 = blockIdx.x*4;
    const float* o0 = out + ((size_t)b*NF + c0)*HWD;
    float acc[4][24];
    #pragma unroll
    for (int ch = 0; ch < 4; ch++)
        #pragma unroll
        for (int f = 0; f < 24; f++) acc[ch][f] = 0.f;
    for (int p = threadIdx.x; p < HWD; p += 128){
        float ov0 = o0[p], ov1 = o0[HWD+p], ov2 = o0[2*HWD+p], ov3 = o0[3*HWD+p];
        #pragma unroll
        for (int f = 0; f < 24; f++){
            float pv = pe[f*HWD + p];
            acc[0][f] += ov0*pv; acc[1][f] += ov1*pv;
            acc[2][f] += ov2*pv; acc[3][f] += ov3*pv;
        }
    }
    __shared__ float red[4][4][24];
    int lane = threadIdx.x & 31, wrp = threadIdx.x >> 5;
    #pragma unroll
    for (int ch = 0; ch < 4; ch++)
        #pragma unroll
        for (int f = 0; f < 24; f++){
            float v = acc[ch][f];
            #pragma unroll
            for (int s = 16; s > 0; s >>= 1) v += __shfl_xor_sync(0xffffffffu, v, s);
            if (lane == 0) red[wrp][ch][f] = v;
        }
    __syncthreads();
    if (threadIdx.x < 96){
        int ch = threadIdx.x / 24, f = threadIdx.x % 24;
        float s = red[0][ch][f] + red[1][ch][f] + red[2][ch][f] + red[3][ch][f];
        cat[b*CATD + 512 + (c0+ch)*24 + f] = s * (1.f/4096.f);
    }
}

// ---------------- host orchestration (3-stream fork/join) ----------------
extern "C" void kernel_launch(void* const* d_in, const int* in_sizes, int n_in,
                              void* d_out, int out_size){
    const float* x      = (const float*)d_in[0];
    const float* inj    = (const float*)d_in[1];
    const float* w_in   = (const float*)d_in[2];
    const float* b_in   = (const float*)d_in[3];
    const float* fl_w1  = (const float*)d_in[4];
    const float* fl_b1  = (const float*)d_in[5];
    const float* fl_w2  = (const float*)d_in[6];
    const float* fl_b2  = (const float*)d_in[7];
    const float* fl_ws  = (const float*)d_in[8];
    const float* fl_bs  = (const float*)d_in[9];
    const float* dyn_w  = (const float*)d_in[10];
    const float* dyn_b  = (const float*)d_in[11];
    const float* pe     = (const float*)d_in[12];
    const float* otl_w1 = (const float*)d_in[13];
    const float* otl_b1 = (const float*)d_in[14];
    const float* otl_w2 = (const float*)d_in[15];
    const float* otl_b2 = (const float*)d_in[16];
    const float* otl_ws = (const float*)d_in[17];
    const float* otl_bs = (const float*)d_in[18];
    const float* ltl_w  = (const float*)d_in[19];
    const float* ltl_b  = (const float*)d_in[20];

    float *p_out0, *p_feat, *p_h, *p_p, *p_pt, *p_injA, *p_injB, *p_latA, *p_latB;
    float *p_cat, *p_partW, *p_partM;
    cudaGetSymbolAddress((void**)&p_out0, g_out);
    cudaGetSymbolAddress((void**)&p_feat, g_feat);
    cudaGetSymbolAddress((void**)&p_h,    g_h);
    cudaGetSymbolAddress((void**)&p_p,    g_p);
    cudaGetSymbolAddress((void**)&p_pt,   g_pt);
    cudaGetSymbolAddress((void**)&p_injA, g_injA);
    cudaGetSymbolAddress((void**)&p_injB, g_injB);
    cudaGetSymbolAddress((void**)&p_latA, g_latA);
    cudaGetSymbolAddress((void**)&p_latB, g_latB);
    cudaGetSymbolAddress((void**)&p_cat,  g_cat);
    cudaGetSymbolAddress((void**)&p_partW, g_partW);
    cudaGetSymbolAddress((void**)&p_partM, g_partM);
    float* po[2] = { p_out0, p_out0 + (size_t)NB*NF*HWD };

    static cudaStream_t sW = nullptr, sO = nullptr;
    static cudaEvent_t ev0, evW[4], evD[4], evO[4];
    if (!sW){
        cudaStreamCreateWithFlags(&sW, cudaStreamNonBlocking);
        cudaStreamCreateWithFlags(&sO, cudaStreamNonBlocking);
        cudaEventCreateWithFlags(&ev0, cudaEventDisableTiming);
        for (int i = 0; i < 4; i++){
            cudaEventCreateWithFlags(&evW[i], cudaEventDisableTiming);
            cudaEventCreateWithFlags(&evD[i], cudaEventDisableTiming);
            cudaEventCreateWithFlags(&evO[i], cudaEventDisableTiming);
        }
        cudaFuncSetAttribute(k_dynH, cudaFuncAttributeMaxDynamicSharedMemorySize, 49152);
        cudaFuncSetAttribute(k_dynO, cudaFuncAttributeMaxDynamicSharedMemorySize, 49152);
    }

    // ---- fork: main(0) -> sW, sO ----
    k_zero<<<16, 512>>>(p_latA);
    cudaEventRecord(ev0, 0);
    cudaStreamWaitEvent(sW, ev0, 0);
    cudaStreamWaitEvent(sO, ev0, 0);

    // ---- weight stream: all 4 iterations of inj chain + p + pt ----
    cudaMemcpyAsync(p_injA, inj, (size_t)NB*LATD*sizeof(float),
                    cudaMemcpyDeviceToDevice, sW);
    {
        float* injC = p_injA; float* injN = p_injB;
        for (int c = 0; c < 4; c++){
            gemm16_part<<<dim3(4,8), 128, 0, sW>>>(injC, LATD, fl_w1, p_partW, LATD, 64, 0, LDW);
            gemm16_part<<<dim3(4,8), 128, 0, sW>>>(injC, LATD, fl_ws, p_partW, LATD, 64, 8, LDW);
            gemm16_part_red<<<dim3(4,8), 128, 0, sW>>>(p_partW, LATD, 8, fl_b1,
                                                       fl_w2, p_partW, LATD, 64, 16, LDW, LDW);
            gemm16_reduce_fin<<<32, 256, 0, sW>>>(p_partW, 8, 16, fl_bs, fl_b2, injN, LATD, LDW);
            gemm16_full<<<(PD + 127)/128, 128, 0, sW>>>(injN, LATD, dyn_w, dyn_b,
                                                        p_p + (size_t)c*NB*PD, PD);
            k_prep<<<dim3(36, 3, NB), dim3(32, 8), 0, sW>>>(p_p + (size_t)c*NB*PD,
                                                            p_pt + (size_t)c*NB*PTS);
            cudaEventRecord(evW[c], sW);
            float* t = injC; injC = injN; injN = t;
        }
    }

    // ---- main image path ----
    k_init_out<<<NB*NF, 256>>>(x, w_in, b_in, po[0]);
    float* latC = p_latA; float* latN = p_latB;

    for (int c = 0; c < 4; c++){
        k_perceive<<<dim3(NB*NF, 3), 256>>>(po[c & 1], p_feat);
        cudaStreamWaitEvent(0, evW[c], 0);
        if (c >= 2) cudaStreamWaitEvent(0, evO[c-2], 0);   // out-buffer reuse guard
        k_dynH<<<dim3(HWD/DTN, NB), 256, 49152>>>(p_pt + (size_t)c*NB*PTS,
                                                  p_p + (size_t)c*NB*PD, p_feat, p_h);
        k_dynO<<<dim3(HWD/DTN, NB), 256, 49152>>>(p_pt + (size_t)c*NB*PTS,
                                                  p_p + (size_t)c*NB*PD, p_feat, p_h,
                                                  po[(c+1) & 1]);
        cudaEventRecord(evD[c], 0);

        // ---- latent stream: freq + cat + otl chain for this iteration ----
        cudaStreamWaitEvent(sO, evD[c], 0);
        k_freq<<<dim3(16, NB), 128, 0, sO>>>(po[(c+1) & 1], pe, p_cat);
        k_copylat<<<32, 256, 0, sO>>>(latC, p_cat);
        const float* w1 = otl_w1 + (size_t)c*CATD*CATD;
        const float* b1 = otl_b1 + (size_t)c*CATD;
        const float* w2 = otl_w2 + (size_t)c*CATD*LATD;
        const float* b2 = otl_b2 + (size_t)c*LATD;
        const float* ws = otl_ws + (size_t)c*CATD*LATD;
        const float* bs = otl_bs + (size_t)c*LATD;
        gemm16_part<<<dim3(16,8), 128, 0, sO>>>(p_cat, CATD, w1, p_partM, CATD, 256, 0, LDM);
        gemm16_part<<<dim3(4,8), 128, 0, sO>>>(p_cat, CATD, ws, p_partM, LATD, 256, 8, LDM);
        gemm16_part_red<<<dim3(4,8), 128, 0, sO>>>(p_partM, CATD, 8, b1,
                                                   w2, p_partM, LATD, 256, 16, LDM, LDM);
        gemm16_reduce_fin<<<32, 256, 0, sO>>>(p_partM, 8, 16, bs, b2, latN, LATD, LDM);
        cudaEventRecord(evO[c], sO);

        float* t = latC; latC = latN; latN = t;
    }

    // ---- join + final projection on main ----
    cudaStreamWaitEvent(0, evO[3], 0);
    gemm16_part<<<dim3(4,8), 128>>>(latC, LATD, ltl_w, p_partW, LATD, 64, 0, LDW);
    gemm16_reduce_fin<<<32, 256>>>(p_partW, 0, 8, ltl_b, nullptr, (float*)d_out, LATD, LDW);
}

// round 12
// speedup vs baseline: 1.8156x; 1.2821x over previous
#include <cuda_runtime.h>
#include <cstdint>

#define NB   16
#define NF   64
#define LATD 512
#define IMG  64
#define HWD  4096
#define FIN  576
#define PD   78016
#define CATD 2048

#define OFF_KIN  0
#define OFF_BIN  36864
#define OFF_KOUT 36928
#define OFF_BOUT 41024
#define OFF_KSK  41088
#define OFF_BSK  77952

#define LDW  (16*LATD)
#define LDM  (16*CATD)
#define MTN  256

typedef unsigned long long ull;

// ---------------- scratch ----------------
__device__ float g_out [2][NB*NF*HWD];
__device__ float g_feat[(size_t)NB*FIN*HWD];
__device__ float g_h   [NB*NF*HWD];
__device__ float g_p   [4][NB*PD];
__device__ float g_injA[NB*LATD], g_injB[NB*LATD];
__device__ float g_latA[NB*LATD], g_latB[NB*LATD];
__device__ float g_cat [NB*CATD];
__device__ float g_partW[24*LDW];
__device__ float g_partM[24*LDM];

__device__ __forceinline__ float lrelu(float v){ return v > 0.f ? v : 0.2f*v; }
__device__ __forceinline__ uint32_t tf32c(float f){
    uint32_t r; asm("cvt.rna.tf32.f32 %0, %1;" : "=r"(r) : "f"(f)); return r;
}

// ---------------- init ----------------
__global__ void k_init_out(const float* __restrict__ x, const float* __restrict__ w_in,
                           const float* __restrict__ b_in, float* __restrict__ out){
    int b = blockIdx.x >> 6, o = blockIdx.x & 63;
    float w0 = w_in[o*3+0], w1 = w_in[o*3+1], w2 = w_in[o*3+2], bb = b_in[o];
    const float* xb = x + (size_t)b*3*HWD;
    float* ob = out + (size_t)blockIdx.x*HWD;
    for (int p = threadIdx.x; p < HWD; p += blockDim.x)
        ob[p] = w0*xb[p] + w1*xb[HWD+p] + w2*xb[2*HWD+p] + bb;
}
__global__ void k_zero(float* p){ p[blockIdx.x*512 + threadIdx.x] = 0.f; }
__global__ void k_copylat(const float* __restrict__ lat, float* __restrict__ cat){
    int idx = blockIdx.x*256 + threadIdx.x;
    int b = idx >> 9, n = idx & 511;
    cat[b*CATD + n] = lat[idx];
}

// ---------------- small GEMM family (unchanged from R10) ----------------
__global__ void __launch_bounds__(128) gemm16_part(
    const float* __restrict__ X, int K, const float* __restrict__ W,
    float* __restrict__ Yp, int N, int kc, int slot0, int ldslot)
{
    __shared__ __align__(16) float Xs[256*16];
    int ks = blockIdx.y, k0 = ks*kc;
    int klen = min(kc, K - k0);
    for (int k = threadIdx.x; k < klen; k += 128){
        #pragma unroll
        for (int b = 0; b < 16; b++) Xs[k*16+b] = X[(size_t)b*K + k0 + k];
    }
    __syncthreads();
    int n = blockIdx.x*128 + threadIdx.x;
    if (n >= N) return;
    float acc[16];
    #pragma unroll
    for (int b = 0; b < 16; b++) acc[b] = 0.f;
    #pragma unroll 4
    for (int k = 0; k < klen; k++){
        float w = W[(size_t)(k0+k)*N + n];
        const float4* xp = (const float4*)(Xs + k*16);
        float4 x0 = xp[0], x1 = xp[1], x2 = xp[2], x3 = xp[3];
        acc[0]+=x0.x*w; acc[1]+=x0.y*w; acc[2]+=x0.z*w; acc[3]+=x0.w*w;
        acc[4]+=x1.x*w; acc[5]+=x1.y*w; acc[6]+=x1.z*w; acc[7]+=x1.w*w;
        acc[8]+=x2.x*w; acc[9]+=x2.y*w; acc[10]+=x2.z*w; acc[11]+=x2.w*w;
        acc[12]+=x3.x*w; acc[13]+=x3.y*w; acc[14]+=x3.z*w; acc[15]+=x3.w*w;
    }
    float* yp = Yp + (size_t)(slot0+ks)*ldslot;
    #pragma unroll
    for (int b = 0; b < 16; b++) yp[(size_t)b*N + n] = acc[b];
}

__global__ void __launch_bounds__(128) gemm16_part_red(
    const float* __restrict__ Ypin, int Kin, int nsl, const float* __restrict__ b1,
    const float* __restrict__ W, float* __restrict__ Yp, int N, int kc,
    int slot0, int ldin, int ldout)
{
    __shared__ __align__(16) float Xs[256*16];
    int ks = blockIdx.y, k0 = ks*kc;
    int klen = min(kc, Kin - k0);
    for (int k = threadIdx.x; k < klen; k += 128){
        float bv = b1[k0 + k];
        #pragma unroll
        for (int b = 0; b < 16; b++){
            float s = bv;
            for (int t = 0; t < nsl; t++)
                s += Ypin[(size_t)t*ldin + (size_t)b*Kin + k0 + k];
            Xs[k*16+b] = lrelu(s);
        }
    }
    __syncthreads();
    int n = blockIdx.x*128 + threadIdx.x;
    if (n >= N) return;
    float acc[16];
    #pragma unroll
    for (int b = 0; b < 16; b++) acc[b] = 0.f;
    #pragma unroll 4
    for (int k = 0; k < klen; k++){
        float w = W[(size_t)(k0+k)*N + n];
        const float4* xp = (const float4*)(Xs + k*16);
        float4 x0 = xp[0], x1 = xp[1], x2 = xp[2], x3 = xp[3];
        acc[0]+=x0.x*w; acc[1]+=x0.y*w; acc[2]+=x0.z*w; acc[3]+=x0.w*w;
        acc[4]+=x1.x*w; acc[5]+=x1.y*w; acc[6]+=x1.z*w; acc[7]+=x1.w*w;
        acc[8]+=x2.x*w; acc[9]+=x2.y*w; acc[10]+=x2.z*w; acc[11]+=x2.w*w;
        acc[12]+=x3.x*w; acc[13]+=x3.y*w; acc[14]+=x3.z*w; acc[15]+=x3.w*w;
    }
    float* yp = Yp + (size_t)(slot0+ks)*ldout;
    #pragma unroll
    for (int b = 0; b < 16; b++) yp[(size_t)b*N + n] = acc[b];
}

__global__ void gemm16_reduce_fin(const float* __restrict__ Yp, int s0, int cnt,
                                  const float* __restrict__ b1, const float* __restrict__ b2,
                                  float* __restrict__ Y, int N, int ldslot)
{
    int idx = blockIdx.x*256 + threadIdx.x;
    if (idx >= 16*N) return;
    int n = idx % N, b = idx / N;
    float s = 0.f;
    for (int t = 0; t < cnt; t++) s += Yp[(size_t)(s0+t)*ldslot + (size_t)b*N + n];
    if (b1) s += b1[n];
    if (b2) s += b2[n];
    Y[idx] = s;
}

__global__ void __launch_bounds__(128) gemm16_full(
    const float* __restrict__ X, int K, const float* __restrict__ W,
    const float* __restrict__ bias, float* __restrict__ Y, int N)
{
    __shared__ __align__(16) float Xs[512*16];
    for (int k = threadIdx.x; k < K; k += 128){
        #pragma unroll
        for (int b = 0; b < 16; b++) Xs[k*16+b] = X[(size_t)b*K + k];
    }
    __syncthreads();
    int n = blockIdx.x*128 + threadIdx.x;
    if (n >= N) return;
    float acc[16];
    #pragma unroll
    for (int b = 0; b < 16; b++) acc[b] = 0.f;
    #pragma unroll 8
    for (int k = 0; k < K; k++){
        float w = W[(size_t)k*N + n];
        const float4* xp = (const float4*)(Xs + k*16);
        float4 x0 = xp[0], x1 = xp[1], x2 = xp[2], x3 = xp[3];
        acc[0]+=x0.x*w; acc[1]+=x0.y*w; acc[2]+=x0.z*w; acc[3]+=x0.w*w;
        acc[4]+=x1.x*w; acc[5]+=x1.y*w; acc[6]+=x1.z*w; acc[7]+=x1.w*w;
        acc[8]+=x2.x*w; acc[9]+=x2.y*w; acc[10]+=x2.z*w; acc[11]+=x2.w*w;
        acc[12]+=x3.x*w; acc[13]+=x3.y*w; acc[14]+=x3.z*w; acc[15]+=x3.w*w;
    }
    float bv = bias[n];
    #pragma unroll
    for (int b = 0; b < 16; b++) Y[(size_t)b*N + n] = acc[b] + bv;
}

// ---------------- perceive + inorm (unchanged) ----------------
__global__ void __launch_bounds__(256) k_perceive(const float* __restrict__ out,
                                                  float* __restrict__ feat){
    __shared__ float xs[64*64];
    __shared__ float rs1[8], rs2[8], bcast[2];
    int bcid = blockIdx.x, gs = blockIdx.y;
    int b = bcid >> 6, c = bcid & 63;
    const float* src = out + (size_t)bcid*HWD;
    for (int p = threadIdx.x; p < HWD; p += 256) xs[p] = src[p];
    __syncthreads();
    int lane = threadIdx.x & 31, wrp = threadIdx.x >> 5;
    for (int g = gs*3; g < gs*3+3; g++){
        float v[16];
        float s1 = 0.f, s2 = 0.f;
        int d = (g == 0) ? 0 : (1 << ((g-1) >> 1));
        int isX = ((g-1) & 1) == 0;
        #pragma unroll
        for (int t = 0; t < 16; t++){
            int p = threadIdx.x + t*256;
            int i = p >> 6, j = p & 63;
            float val;
            if (g == 0){
                val = xs[p];
            } else {
                int im = i-d, ip = i+d, jm = j-d, jp = j+d;
                bool imv = im >= 0, ipv = ip < 64, jmv = jm >= 0, jpv = jp < 64;
                if (isX){
                    float t0 = ((imv&&jpv) ? xs[im*64+jp] : 0.f) - ((imv&&jmv) ? xs[im*64+jm] : 0.f);
                    float t1 = (jpv ? xs[i*64+jp] : 0.f)         - (jmv ? xs[i*64+jm] : 0.f);
                    float t2 = ((ipv&&jpv) ? xs[ip*64+jp] : 0.f) - ((ipv&&jmv) ? xs[ip*64+jm] : 0.f);
                    val = 0.125f*(t0 + 2.f*t1 + t2);
                } else {
                    float t0 = ((ipv&&jmv) ? xs[ip*64+jm] : 0.f) - ((imv&&jmv) ? xs[im*64+jm] : 0.f);
                    float t1 = (ipv ? xs[ip*64+j] : 0.f)         - (imv ? xs[im*64+j] : 0.f);
                    float t2 = ((ipv&&jpv) ? xs[ip*64+jp] : 0.f) - ((imv&&jpv) ? xs[im*64+jp] : 0.f);
                    val = 0.125f*(t0 + 2.f*t1 + t2);
                }
            }
            v[t] = val; s1 += val; s2 += val*val;
        }
        #pragma unroll
        for (int s = 16; s > 0; s >>= 1){
            s1 += __shfl_xor_sync(0xffffffffu, s1, s);
            s2 += __shfl_xor_sync(0xffffffffu, s2, s);
        }
        if (lane == 0){ rs1[wrp] = s1; rs2[wrp] = s2; }
        __syncthreads();
        if (threadIdx.x == 0){
            float a = 0.f, q = 0.f;
            #pragma unroll
            for (int w = 0; w < 8; w++){ a += rs1[w]; q += rs2[w]; }
            float mean = a*(1.f/4096.f);
            float var  = q*(1.f/4096.f) - mean*mean;
            bcast[0] = mean; bcast[1] = rsqrtf(var + 1e-5f);
        }
        __syncthreads();
        float mean = bcast[0], inv = bcast[1];
        float* dst = feat + ((size_t)b*FIN + g*64 + c)*HWD;
        #pragma unroll
        for (int t = 0; t < 16; t++)
            dst[threadIdx.x + t*256] = (v[t]-mean)*inv;
        __syncthreads();
    }
}

// ---------------- dyn-conv GEMMs on mma.sync tf32 ----------------
// Block 256 thr (8 warps), per block: C[64, 256] for batch b, n-tile.
// Warp w owns 32 n-cols; per warp: 4 m-steps(16) x 4 n-steps(8), m16n8k8 frags.
// As: 64x32 tf32, stride 36 (bank = 4g+tig, bijective); Bs: 32x256, stride 264
// (bank = 8*tig+g, bijective). 43008 B static smem.
struct SmemDyn {
    uint32_t As[64*36];
    uint32_t Bs[32*264];
};

__device__ __forceinline__ void fill_A(const float* __restrict__ A, int lda, int k0,
                                       uint32_t* As, int tid){
    #pragma unroll
    for (int q = 0; q < 2; q++){
        int fid = q*256 + tid;
        int row = fid >> 3, c4 = fid & 7;
        float4 v = *(const float4*)(A + (size_t)row*lda + k0 + c4*4);
        uint4 t; t.x = tf32c(v.x); t.y = tf32c(v.y); t.z = tf32c(v.z); t.w = tf32c(v.w);
        *(uint4*)(As + row*36 + c4*4) = t;
    }
}
__device__ __forceinline__ void fill_B(const float* __restrict__ B, int k0,
                                       uint32_t* Bs, int tid){
    #pragma unroll
    for (int q = 0; q < 8; q++){
        int fid = q*256 + tid;
        int row = fid >> 6, c4 = fid & 63;
        float4 v = *(const float4*)(B + (size_t)(k0+row)*HWD + c4*4);
        uint4 t; t.x = tf32c(v.x); t.y = tf32c(v.y); t.z = tf32c(v.z); t.w = tf32c(v.w);
        *(uint4*)(Bs + row*264 + c4*4) = t;
    }
}

__device__ __forceinline__ void mma_tile(const uint32_t* As, const uint32_t* Bs,
                                         float acc[4][4][4], int g, int tig, int nbase){
    #pragma unroll
    for (int k8 = 0; k8 < 4; k8++){
        uint32_t a[4][4];
        #pragma unroll
        for (int ms = 0; ms < 4; ms++){
            int r0 = ms*16 + g;
            a[ms][0] = As[r0*36 + k8*8 + tig];
            a[ms][1] = As[(r0+8)*36 + k8*8 + tig];
            a[ms][2] = As[r0*36 + k8*8 + tig + 4];
            a[ms][3] = As[(r0+8)*36 + k8*8 + tig + 4];
        }
        #pragma unroll
        for (int ns = 0; ns < 4; ns++){
            uint32_t b0 = Bs[(k8*8+tig)*264 + nbase + ns*8 + g];
            uint32_t b1 = Bs[(k8*8+tig+4)*264 + nbase + ns*8 + g];
            #pragma unroll
            for (int ms = 0; ms < 4; ms++){
                asm volatile("mma.sync.aligned.m16n8k8.row.col.f32.tf32.tf32.f32 "
                    "{%0,%1,%2,%3}, {%4,%5,%6,%7}, {%8,%9}, {%0,%1,%2,%3};"
                    : "+f"(acc[ms][ns][0]), "+f"(acc[ms][ns][1]),
                      "+f"(acc[ms][ns][2]), "+f"(acc[ms][ns][3])
                    : "r"(a[ms][0]), "r"(a[ms][1]), "r"(a[ms][2]), "r"(a[ms][3]),
                      "r"(b0), "r"(b1));
            }
        }
    }
}

__global__ void __launch_bounds__(256, 2) k_dynHm(
    const float* __restrict__ p, const float* __restrict__ feat,
    float* __restrict__ h)
{
    __shared__ SmemDyn sm;
    int b = blockIdx.y, n0 = blockIdx.x*MTN;
    int tid = threadIdx.x, w = tid >> 5, lane = tid & 31;
    int g = lane >> 2, tig = lane & 3;
    const float* pb = p + (size_t)b*PD;
    const float* featb = feat + (size_t)b*FIN*HWD + n0;

    float acc[4][4][4];
    #pragma unroll
    for (int ms = 0; ms < 4; ms++)
        #pragma unroll
        for (int ns = 0; ns < 4; ns++)
            #pragma unroll
            for (int r = 0; r < 4; r++) acc[ms][ns][r] = 0.f;

    for (int k0 = 0; k0 < FIN; k0 += 32){
        __syncthreads();
        fill_A(pb + OFF_KIN, FIN, k0, sm.As, tid);
        fill_B(featb, k0, sm.Bs, tid);
        __syncthreads();
        mma_tile(sm.As, sm.Bs, acc, g, tig, w*32);
    }

    #pragma unroll
    for (int ms = 0; ms < 4; ms++){
        int m = ms*16 + g;
        float bi0 = pb[OFF_BIN + m], bi1 = pb[OFF_BIN + m + 8];
        #pragma unroll
        for (int ns = 0; ns < 4; ns++){
            int n = n0 + w*32 + ns*8 + 2*tig;
            float2 v0, v1;
            v0.x = lrelu(acc[ms][ns][0] + bi0); v0.y = lrelu(acc[ms][ns][1] + bi0);
            v1.x = lrelu(acc[ms][ns][2] + bi1); v1.y = lrelu(acc[ms][ns][3] + bi1);
            *(float2*)(h + ((size_t)(b*NF + m))*HWD + n)     = v0;
            *(float2*)(h + ((size_t)(b*NF + m + 8))*HWD + n) = v1;
        }
    }
}

__global__ void __launch_bounds__(256, 2) k_dynOm(
    const float* __restrict__ p, const float* __restrict__ feat,
    const float* __restrict__ h, float* __restrict__ outp)
{
    __shared__ SmemDyn sm;
    int b = blockIdx.y, n0 = blockIdx.x*MTN;
    int tid = threadIdx.x, w = tid >> 5, lane = tid & 31;
    int g = lane >> 2, tig = lane & 3;
    const float* pb = p + (size_t)b*PD;
    const float* featb = feat + (size_t)b*FIN*HWD + n0;
    const float* hb = h + (size_t)b*NF*HWD + n0;

    float acc[4][4][4];
    #pragma unroll
    for (int ms = 0; ms < 4; ms++)
        #pragma unroll
        for (int ns = 0; ns < 4; ns++)
            #pragma unroll
            for (int r = 0; r < 4; r++) acc[ms][ns][r] = 0.f;

    for (int k0 = 0; k0 < FIN; k0 += 32){
        __syncthreads();
        fill_A(pb + OFF_KSK, FIN, k0, sm.As, tid);
        fill_B(featb, k0, sm.Bs, tid);
        __syncthreads();
        mma_tile(sm.As, sm.Bs, acc, g, tig, w*32);
    }
    for (int k0 = 0; k0 < 64; k0 += 32){
        __syncthreads();
        fill_A(pb + OFF_KOUT, 64, k0, sm.As, tid);
        fill_B(hb, k0, sm.Bs, tid);
        __syncthreads();
        mma_tile(sm.As, sm.Bs, acc, g, tig, w*32);
    }

    #pragma unroll
    for (int ms = 0; ms < 4; ms++){
        int m = ms*16 + g;
        float bi0 = pb[OFF_BOUT + m]     + pb[OFF_BSK + m];
        float bi1 = pb[OFF_BOUT + m + 8] + pb[OFF_BSK + m + 8];
        #pragma unroll
        for (int ns = 0; ns < 4; ns++){
            int n = n0 + w*32 + ns*8 + 2*tig;
            float2 v0, v1;
            v0.x = acc[ms][ns][0] + bi0; v0.y = acc[ms][ns][1] + bi0;
            v1.x = acc[ms][ns][2] + bi1; v1.y = acc[ms][ns][3] + bi1;
            *(float2*)(outp + ((size_t)(b*NF + m))*HWD + n)     = v0;
            *(float2*)(outp + ((size_t)(b*NF + m + 8))*HWD + n) = v1;
        }
    }
}

// ---------------- freq ----------------
__global__ void __launch_bounds__(128) k_freq(const float* __restrict__ out,
                                              const float* __restrict__ pe,
                                              float* __restrict__ cat){
    int b = blockIdx.y;
    int c0 = blockIdx.x*4;
    const float* o0 = out + ((size_t)b*NF + c0)*HWD;
    float acc[4][24];
    #pragma unroll
    for (int ch = 0; ch < 4; ch++)
        #pragma unroll
        for (int f = 0; f < 24; f++) acc[ch][f] = 0.f;
    for (int p = threadIdx.x; p < HWD; p += 128){
        float ov0 = o0[p], ov1 = o0[HWD+p], ov2 = o0[2*HWD+p], ov3 = o0[3*HWD+p];
        #pragma unroll
        for (int f = 0; f < 24; f++){
            float pv = pe[f*HWD + p];
            acc[0][f] += ov0*pv; acc[1][f] += ov1*pv;
            acc[2][f] += ov2*pv; acc[3][f] += ov3*pv;
        }
    }
    __shared__ float red[4][4][24];
    int lane = threadIdx.x & 31, wrp = threadIdx.x >> 5;
    #pragma unroll
    for (int ch = 0; ch < 4; ch++)
        #pragma unroll
        for (int f = 0; f < 24; f++){
            float v = acc[ch][f];
            #pragma unroll
            for (int s = 16; s > 0; s >>= 1) v += __shfl_xor_sync(0xffffffffu, v, s);
            if (lane == 0) red[wrp][ch][f] = v;
        }
    __syncthreads();
    if (threadIdx.x < 96){
        int ch = threadIdx.x / 24, f = threadIdx.x % 24;
        float s = red[0][ch][f] + red[1][ch][f] + red[2][ch][f] + red[3][ch][f];
        cat[b*CATD + 512 + (c0+ch)*24 + f] = s * (1.f/4096.f);
    }
}

// ---------------- host orchestration (3-stream fork/join) ----------------
extern "C" void kernel_launch(void* const* d_in, const int* in_sizes, int n_in,
                              void* d_out, int out_size){
    const float* x      = (const float*)d_in[0];
    const float* inj    = (const float*)d_in[1];
    const float* w_in   = (const float*)d_in[2];
    const float* b_in   = (const float*)d_in[3];
    const float* fl_w1  = (const float*)d_in[4];
    const float* fl_b1  = (const float*)d_in[5];
    const float* fl_w2  = (const float*)d_in[6];
    const float* fl_b2  = (const float*)d_in[7];
    const float* fl_ws  = (const float*)d_in[8];
    const float* fl_bs  = (const float*)d_in[9];
    const float* dyn_w  = (const float*)d_in[10];
    const float* dyn_b  = (const float*)d_in[11];
    const float* pe     = (const float*)d_in[12];
    const float* otl_w1 = (const float*)d_in[13];
    const float* otl_b1 = (const float*)d_in[14];
    const float* otl_w2 = (const float*)d_in[15];
    const float* otl_b2 = (const float*)d_in[16];
    const float* otl_ws = (const float*)d_in[17];
    const float* otl_bs = (const float*)d_in[18];
    const float* ltl_w  = (const float*)d_in[19];
    const float* ltl_b  = (const float*)d_in[20];

    float *p_out0, *p_feat, *p_h, *p_p, *p_injA, *p_injB, *p_latA, *p_latB;
    float *p_cat, *p_partW, *p_partM;
    cudaGetSymbolAddress((void**)&p_out0, g_out);
    cudaGetSymbolAddress((void**)&p_feat, g_feat);
    cudaGetSymbolAddress((void**)&p_h,    g_h);
    cudaGetSymbolAddress((void**)&p_p,    g_p);
    cudaGetSymbolAddress((void**)&p_injA, g_injA);
    cudaGetSymbolAddress((void**)&p_injB, g_injB);
    cudaGetSymbolAddress((void**)&p_latA, g_latA);
    cudaGetSymbolAddress((void**)&p_latB, g_latB);
    cudaGetSymbolAddress((void**)&p_cat,  g_cat);
    cudaGetSymbolAddress((void**)&p_partW, g_partW);
    cudaGetSymbolAddress((void**)&p_partM, g_partM);
    float* po[2] = { p_out0, p_out0 + (size_t)NB*NF*HWD };

    static cudaStream_t sW = nullptr, sO = nullptr;
    static cudaEvent_t ev0, evW[4], evD[4], evO[4];
    if (!sW){
        cudaStreamCreateWithFlags(&sW, cudaStreamNonBlocking);
        cudaStreamCreateWithFlags(&sO, cudaStreamNonBlocking);
        cudaEventCreateWithFlags(&ev0, cudaEventDisableTiming);
        for (int i = 0; i < 4; i++){
            cudaEventCreateWithFlags(&evW[i], cudaEventDisableTiming);
            cudaEventCreateWithFlags(&evD[i], cudaEventDisableTiming);
            cudaEventCreateWithFlags(&evO[i], cudaEventDisableTiming);
        }
    }

    // ---- fork ----
    k_zero<<<16, 512>>>(p_latA);
    cudaEventRecord(ev0, 0);
    cudaStreamWaitEvent(sW, ev0, 0);
    cudaStreamWaitEvent(sO, ev0, 0);

    // ---- weight stream: 4 iterations of inj chain + p ----
    cudaMemcpyAsync(p_injA, inj, (size_t)NB*LATD*sizeof(float),
                    cudaMemcpyDeviceToDevice, sW);
    {
        float* injC = p_injA; float* injN = p_injB;
        for (int c = 0; c < 4; c++){
            gemm16_part<<<dim3(4,8), 128, 0, sW>>>(injC, LATD, fl_w1, p_partW, LATD, 64, 0, LDW);
            gemm16_part<<<dim3(4,8), 128, 0, sW>>>(injC, LATD, fl_ws, p_partW, LATD, 64, 8, LDW);
            gemm16_part_red<<<dim3(4,8), 128, 0, sW>>>(p_partW, LATD, 8, fl_b1,
                                                       fl_w2, p_partW, LATD, 64, 16, LDW, LDW);
            gemm16_reduce_fin<<<32, 256, 0, sW>>>(p_partW, 8, 16, fl_bs, fl_b2, injN, LATD, LDW);
            gemm16_full<<<(PD + 127)/128, 128, 0, sW>>>(injN, LATD, dyn_w, dyn_b,
                                                        p_p + (size_t)c*NB*PD, PD);
            cudaEventRecord(evW[c], sW);
            float* t = injC; injC = injN; injN = t;
        }
    }

    // ---- main image path ----
    k_init_out<<<NB*NF, 256>>>(x, w_in, b_in, po[0]);
    float* latC = p_latA; float* latN = p_latB;

    for (int c = 0; c < 4; c++){
        k_perceive<<<dim3(NB*NF, 3), 256>>>(po[c & 1], p_feat);
        cudaStreamWaitEvent(0, evW[c], 0);
        if (c >= 2) cudaStreamWaitEvent(0, evO[c-2], 0);
        k_dynHm<<<dim3(HWD/MTN, NB), 256>>>(p_p + (size_t)c*NB*PD, p_feat, p_h);
        k_dynOm<<<dim3(HWD/MTN, NB), 256>>>(p_p + (size_t)c*NB*PD, p_feat, p_h,
                                            po[(c+1) & 1]);
        cudaEventRecord(evD[c], 0);

        cudaStreamWaitEvent(sO, evD[c], 0);
        k_freq<<<dim3(16, NB), 128, 0, sO>>>(po[(c+1) & 1], pe, p_cat);
        k_copylat<<<32, 256, 0, sO>>>(latC, p_cat);
        const float* w1 = otl_w1 + (size_t)c*CATD*CATD;
        const float* b1 = otl_b1 + (size_t)c*CATD;
        const float* w2 = otl_w2 + (size_t)c*CATD*LATD;
        const float* b2 = otl_b2 + (size_t)c*LATD;
        const float* ws = otl_ws + (size_t)c*CATD*LATD;
        const float* bs = otl_bs + (size_t)c*LATD;
        gemm16_part<<<dim3(16,8), 128, 0, sO>>>(p_cat, CATD, w1, p_partM, CATD, 256, 0, LDM);
        gemm16_part<<<dim3(4,8), 128, 0, sO>>>(p_cat, CATD, ws, p_partM, LATD, 256, 8, LDM);
        gemm16_part_red<<<dim3(4,8), 128, 0, sO>>>(p_partM, CATD, 8, b1,
                                                   w2, p_partM, LATD, 256, 16, LDM, LDM);
        gemm16_reduce_fin<<<32, 256, 0, sO>>>(p_partM, 8, 16, bs, b2, latN, LATD, LDM);
        cudaEventRecord(evO[c], sO);

        float* t = latC; latC = latN; latN = t;
    }

    // ---- join + final ----
    cudaStreamWaitEvent(0, evO[3], 0);
    gemm16_part<<<dim3(4,8), 128>>>(latC, LATD, ltl_w, p_partW, LATD, 64, 0, LDW);
    gemm16_reduce_fin<<<32, 256>>>(p_partW, 0, 8, ltl_b, nullptr, (float*)d_out, LATD, LDW);
}

// round 14
// speedup vs baseline: 1.9717x; 1.0860x over previous
#include <cuda_runtime.h>
#include <cstdint>

#define NB   16
#define NF   64
#define LATD 512
#define IMG  64
#define HWD  4096
#define FIN  576
#define PD   78016
#define CATD 2048

#define OFF_KIN  0
#define OFF_BIN  36864
#define OFF_KOUT 36928
#define OFF_BOUT 41024
#define OFF_KSK  41088
#define OFF_BSK  77952

#define LDW  (16*LATD)
#define LDM  (16*CATD)
#define MTN  256

// dyn smem layout (uint32 offsets)
#define DYN_AS0 0
#define DYN_AS1 2304
#define DYN_BS  4608
#define DYN_BH  13056
#define DYN_TOT 21504   // *4 = 86016 B

typedef unsigned long long ull;

// ---------------- scratch ----------------
__device__ float g_out [2][NB*NF*HWD];
__device__ float g_feat[(size_t)NB*FIN*HWD];
__device__ float g_p   [4][NB*PD];
__device__ float g_injA[NB*LATD], g_injB[NB*LATD];
__device__ float g_latA[NB*LATD], g_latB[NB*LATD];
__device__ float g_cat [NB*CATD];
__device__ float g_partW[24*LDW];
__device__ float g_partM[24*LDM];

__device__ __forceinline__ float lrelu(float v){ return v > 0.f ? v : 0.2f*v; }
__device__ __forceinline__ uint32_t tf32c(float f){
    uint32_t r; asm("cvt.rna.tf32.f32 %0, %1;" : "=r"(r) : "f"(f)); return r;
}

// ---------------- init ----------------
__global__ void k_init_out(const float* __restrict__ x, const float* __restrict__ w_in,
                           const float* __restrict__ b_in, float* __restrict__ out){
    int b = blockIdx.x >> 6, o = blockIdx.x & 63;
    float w0 = w_in[o*3+0], w1 = w_in[o*3+1], w2 = w_in[o*3+2], bb = b_in[o];
    const float* xb = x + (size_t)b*3*HWD;
    float* ob = out + (size_t)blockIdx.x*HWD;
    for (int p = threadIdx.x; p < HWD; p += blockDim.x)
        ob[p] = w0*xb[p] + w1*xb[HWD+p] + w2*xb[2*HWD+p] + bb;
}
__global__ void k_zero(float* p){ p[blockIdx.x*512 + threadIdx.x] = 0.f; }

// ---------------- small GEMM family ----------------
__global__ void __launch_bounds__(128) gemm16_part2(
    const float* __restrict__ X, int K,
    const float* __restrict__ W0, int N0, int slot00,
    const float* __restrict__ W1, int N1, int slot01,
    int kc, float* __restrict__ Yp, int ldslot)
{
    const float* W = blockIdx.z ? W1 : W0;
    int N = blockIdx.z ? N1 : N0;
    int slot0 = blockIdx.z ? slot01 : slot00;
    if (blockIdx.x*128 >= N) return;
    __shared__ __align__(16) float Xs[256*16];
    int ks = blockIdx.y, k0 = ks*kc;
    int klen = min(kc, K - k0);
    for (int k = threadIdx.x; k < klen; k += 128){
        #pragma unroll
        for (int b = 0; b < 16; b++) Xs[k*16+b] = X[(size_t)b*K + k0 + k];
    }
    __syncthreads();
    int n = blockIdx.x*128 + threadIdx.x;
    if (n >= N) return;
    float acc[16];
    #pragma unroll
    for (int b = 0; b < 16; b++) acc[b] = 0.f;
    #pragma unroll 4
    for (int k = 0; k < klen; k++){
        float w = W[(size_t)(k0+k)*N + n];
        const float4* xp = (const float4*)(Xs + k*16);
        float4 x0 = xp[0], x1 = xp[1], x2 = xp[2], x3 = xp[3];
        acc[0]+=x0.x*w; acc[1]+=x0.y*w; acc[2]+=x0.z*w; acc[3]+=x0.w*w;
        acc[4]+=x1.x*w; acc[5]+=x1.y*w; acc[6]+=x1.z*w; acc[7]+=x1.w*w;
        acc[8]+=x2.x*w; acc[9]+=x2.y*w; acc[10]+=x2.z*w; acc[11]+=x2.w*w;
        acc[12]+=x3.x*w; acc[13]+=x3.y*w; acc[14]+=x3.z*w; acc[15]+=x3.w*w;
    }
    float* yp = Yp + (size_t)(slot0+ks)*ldslot;
    #pragma unroll
    for (int b = 0; b < 16; b++) yp[(size_t)b*N + n] = acc[b];
}

__global__ void __launch_bounds__(128) gemm16_part_red(
    const float* __restrict__ Ypin, int Kin, int nsl, const float* __restrict__ b1,
    const float* __restrict__ W, float* __restrict__ Yp, int N, int kc,
    int slot0, int ldin, int ldout)
{
    __shared__ __align__(16) float Xs[256*16];
    int ks = blockIdx.y, k0 = ks*kc;
    int klen = min(kc, Kin - k0);
    for (int k = threadIdx.x; k < klen; k += 128){
        float bv = b1[k0 + k];
        #pragma unroll
        for (int b = 0; b < 16; b++){
            float s = bv;
            for (int t = 0; t < nsl; t++)
                s += Ypin[(size_t)t*ldin + (size_t)b*Kin + k0 + k];
            Xs[k*16+b] = lrelu(s);
        }
    }
    __syncthreads();
    int n = blockIdx.x*128 + threadIdx.x;
    if (n >= N) return;
    float acc[16];
    #pragma unroll
    for (int b = 0; b < 16; b++) acc[b] = 0.f;
    #pragma unroll 4
    for (int k = 0; k < klen; k++){
        float w = W[(size_t)(k0+k)*N + n];
        const float4* xp = (const float4*)(Xs + k*16);
        float4 x0 = xp[0], x1 = xp[1], x2 = xp[2], x3 = xp[3];
        acc[0]+=x0.x*w; acc[1]+=x0.y*w; acc[2]+=x0.z*w; acc[3]+=x0.w*w;
        acc[4]+=x1.x*w; acc[5]+=x1.y*w; acc[6]+=x1.z*w; acc[7]+=x1.w*w;
        acc[8]+=x2.x*w; acc[9]+=x2.y*w; acc[10]+=x2.z*w; acc[11]+=x2.w*w;
        acc[12]+=x3.x*w; acc[13]+=x3.y*w; acc[14]+=x3.z*w; acc[15]+=x3.w*w;
    }
    float* yp = Yp + (size_t)(slot0+ks)*ldout;
    #pragma unroll
    for (int b = 0; b < 16; b++) yp[(size_t)b*N + n] = acc[b];
}

__global__ void gemm16_reduce_fin(const float* __restrict__ Yp, int s0, int cnt,
                                  const float* __restrict__ b1, const float* __restrict__ b2,
                                  float* __restrict__ Y, int N, int ldslot)
{
    int idx = blockIdx.x*256 + threadIdx.x;
    if (idx >= 16*N) return;
    int n = idx % N, b = idx / N;
    float s = 0.f;
    for (int t = 0; t < cnt; t++) s += Yp[(size_t)(s0+t)*ldslot + (size_t)b*N + n];
    if (b1) s += b1[n];
    if (b2) s += b2[n];
    Y[idx] = s;
}

__global__ void __launch_bounds__(128) gemm16_full(
    const float* __restrict__ X, int K, const float* __restrict__ W,
    const float* __restrict__ bias, float* __restrict__ Y, int N)
{
    __shared__ __align__(16) float Xs[512*16];
    for (int k = threadIdx.x; k < K; k += 128){
        #pragma unroll
        for (int b = 0; b < 16; b++) Xs[k*16+b] = X[(size_t)b*K + k];
    }
    __syncthreads();
    int n = blockIdx.x*128 + threadIdx.x;
    if (n >= N) return;
    float acc[16];
    #pragma unroll
    for (int b = 0; b < 16; b++) acc[b] = 0.f;
    #pragma unroll 8
    for (int k = 0; k < K; k++){
        float w = W[(size_t)k*N + n];
        const float4* xp = (const float4*)(Xs + k*16);
        float4 x0 = xp[0], x1 = xp[1], x2 = xp[2], x3 = xp[3];
        acc[0]+=x0.x*w; acc[1]+=x0.y*w; acc[2]+=x0.z*w; acc[3]+=x0.w*w;
        acc[4]+=x1.x*w; acc[5]+=x1.y*w; acc[6]+=x1.z*w; acc[7]+=x1.w*w;
        acc[8]+=x2.x*w; acc[9]+=x2.y*w; acc[10]+=x2.z*w; acc[11]+=x2.w*w;
        acc[12]+=x3.x*w; acc[13]+=x3.y*w; acc[14]+=x3.z*w; acc[15]+=x3.w*w;
    }
    float bv = bias[n];
    #pragma unroll
    for (int b = 0; b < 16; b++) Y[(size_t)b*N + n] = acc[b] + bv;
}

// ---------------- perceive + inorm ----------------
__global__ void __launch_bounds__(256) k_perceive(const float* __restrict__ out,
                                                  float* __restrict__ feat){
    __shared__ float xs[64*64];
    __shared__ float rs1[8], rs2[8], bcast[2];
    int bcid = blockIdx.x, gs = blockIdx.y;
    int b = bcid >> 6, c = bcid & 63;
    const float* src = out + (size_t)bcid*HWD;
    for (int p = threadIdx.x; p < HWD; p += 256) xs[p] = src[p];
    __syncthreads();
    int lane = threadIdx.x & 31, wrp = threadIdx.x >> 5;
    for (int g = gs*3; g < gs*3+3; g++){
        float v[16];
        float s1 = 0.f, s2 = 0.f;
        int d = (g == 0) ? 0 : (1 << ((g-1) >> 1));
        int isX = ((g-1) & 1) == 0;
        #pragma unroll
        for (int t = 0; t < 16; t++){
            int p = threadIdx.x + t*256;
            int i = p >> 6, j = p & 63;
            float val;
            if (g == 0){
                val = xs[p];
            } else {
                int im = i-d, ip = i+d, jm = j-d, jp = j+d;
                bool imv = im >= 0, ipv = ip < 64, jmv = jm >= 0, jpv = jp < 64;
                if (isX){
                    float t0 = ((imv&&jpv) ? xs[im*64+jp] : 0.f) - ((imv&&jmv) ? xs[im*64+jm] : 0.f);
                    float t1 = (jpv ? xs[i*64+jp] : 0.f)         - (jmv ? xs[i*64+jm] : 0.f);
                    float t2 = ((ipv&&jpv) ? xs[ip*64+jp] : 0.f) - ((ipv&&jmv) ? xs[ip*64+jm] : 0.f);
                    val = 0.125f*(t0 + 2.f*t1 + t2);
                } else {
                    float t0 = ((ipv&&jmv) ? xs[ip*64+jm] : 0.f) - ((imv&&jmv) ? xs[im*64+jm] : 0.f);
                    float t1 = (ipv ? xs[ip*64+j] : 0.f)         - (imv ? xs[im*64+j] : 0.f);
                    float t2 = ((ipv&&jpv) ? xs[ip*64+jp] : 0.f) - ((imv&&jpv) ? xs[im*64+jp] : 0.f);
                    val = 0.125f*(t0 + 2.f*t1 + t2);
                }
            }
            v[t] = val; s1 += val; s2 += val*val;
        }
        #pragma unroll
        for (int s = 16; s > 0; s >>= 1){
            s1 += __shfl_xor_sync(0xffffffffu, s1, s);
            s2 += __shfl_xor_sync(0xffffffffu, s2, s);
        }
        if (lane == 0){ rs1[wrp] = s1; rs2[wrp] = s2; }
        __syncthreads();
        if (threadIdx.x == 0){
            float a = 0.f, q = 0.f;
            #pragma unroll
            for (int w = 0; w < 8; w++){ a += rs1[w]; q += rs2[w]; }
            float mean = a*(1.f/4096.f);
            float var  = q*(1.f/4096.f) - mean*mean;
            bcast[0] = mean; bcast[1] = rsqrtf(var + 1e-5f);
        }
        __syncthreads();
        float mean = bcast[0], inv = bcast[1];
        float* dst = feat + ((size_t)b*FIN + g*64 + c)*HWD;
        #pragma unroll
        for (int t = 0; t < 16; t++)
            dst[threadIdx.x + t*256] = (v[t]-mean)*inv;
        __syncthreads();
    }
}

// ---------------- fused dyn conv on mma.sync tf32 ----------------
__device__ __forceinline__ void fill_A(const float* __restrict__ A, int lda, int k0,
                                       uint32_t* As, int tid){
    #pragma unroll
    for (int q = 0; q < 2; q++){
        int fid = q*256 + tid;
        int row = fid >> 3, c4 = fid & 7;
        float4 v = *(const float4*)(A + (size_t)row*lda + k0 + c4*4);
        uint4 t; t.x = tf32c(v.x); t.y = tf32c(v.y); t.z = tf32c(v.z); t.w = tf32c(v.w);
        *(uint4*)(As + row*36 + c4*4) = t;
    }
}
__device__ __forceinline__ void fill_B(const float* __restrict__ B, int k0,
                                       uint32_t* Bs, int tid){
    #pragma unroll
    for (int q = 0; q < 8; q++){
        int fid = q*256 + tid;
        int row = fid >> 6, c4 = fid & 63;
        float4 v = *(const float4*)(B + (size_t)(k0+row)*HWD + c4*4);
        uint4 t; t.x = tf32c(v.x); t.y = tf32c(v.y); t.z = tf32c(v.z); t.w = tf32c(v.w);
        *(uint4*)(Bs + row*264 + c4*4) = t;
    }
}
__device__ __forceinline__ void mma_tile(const uint32_t* As, const uint32_t* Bs,
                                         float acc[4][4][4], int g, int tig, int nbase){
    #pragma unroll
    for (int k8 = 0; k8 < 4; k8++){
        uint32_t a[4][4];
        #pragma unroll
        for (int ms = 0; ms < 4; ms++){
            int r0 = ms*16 + g;
            a[ms][0] = As[r0*36 + k8*8 + tig];
            a[ms][1] = As[(r0+8)*36 + k8*8 + tig];
            a[ms][2] = As[r0*36 + k8*8 + tig + 4];
            a[ms][3] = As[(r0+8)*36 + k8*8 + tig + 4];
        }
        #pragma unroll
        for (int ns = 0; ns < 4; ns++){
            uint32_t b0 = Bs[(k8*8+tig)*264 + nbase + ns*8 + g];
            uint32_t b1 = Bs[(k8*8+tig+4)*264 + nbase + ns*8 + g];
            #pragma unroll
            for (int ms = 0; ms < 4; ms++){
                asm volatile("mma.sync.aligned.m16n8k8.row.col.f32.tf32.tf32.f32 "
                    "{%0,%1,%2,%3}, {%4,%5,%6,%7}, {%8,%9}, {%0,%1,%2,%3};"
                    : "+f"(acc[ms][ns][0]), "+f"(acc[ms][ns][1]),
                      "+f"(acc[ms][ns][2]), "+f"(acc[ms][ns][3])
                    : "r"(a[ms][0]), "r"(a[ms][1]), "r"(a[ms][2]), "r"(a[ms][3]),
                      "r"(b0), "r"(b1));
            }
        }
    }
}

__global__ void __launch_bounds__(256, 1) k_dynF(
    const float* __restrict__ p, const float* __restrict__ feat,
    float* __restrict__ outp)
{
    extern __shared__ uint32_t sm[];
    uint32_t* As0 = sm + DYN_AS0;
    uint32_t* As1 = sm + DYN_AS1;
    uint32_t* Bs  = sm + DYN_BS;
    uint32_t* Bh  = sm + DYN_BH;

    int b = blockIdx.y, n0 = blockIdx.x*MTN;
    int tid = threadIdx.x, w = tid >> 5, lane = tid & 31;
    int g = lane >> 2, tig = lane & 3;
    const float* pb = p + (size_t)b*PD;
    const float* featb = feat + (size_t)b*FIN*HWD + n0;

    float accH[4][4][4], accS[4][4][4];
    #pragma unroll
    for (int ms = 0; ms < 4; ms++)
        #pragma unroll
        for (int ns = 0; ns < 4; ns++)
            #pragma unroll
            for (int r = 0; r < 4; r++){ accH[ms][ns][r] = 0.f; accS[ms][ns][r] = 0.f; }

    // GEMM1: accH = kin@feat, accS = ksk@feat (feat read once)
    for (int k0 = 0; k0 < FIN; k0 += 32){
        __syncthreads();
        fill_A(pb + OFF_KIN, FIN, k0, As0, tid);
        fill_A(pb + OFF_KSK, FIN, k0, As1, tid);
        fill_B(featb, k0, Bs, tid);
        __syncthreads();
        mma_tile(As0, Bs, accH, g, tig, w*32);
        mma_tile(As1, Bs, accS, g, tig, w*32);
    }

    // GEMM2: accS += kout @ lrelu(accH + b_in), h staged through smem (2 chunks)
    #pragma unroll
    for (int ck = 0; ck < 2; ck++){
        __syncthreads();
        #pragma unroll
        for (int msL = 0; msL < 2; msL++){
            int ms = ck*2 + msL;
            float blo = pb[OFF_BIN + ms*16 + g];
            float bhi = pb[OFF_BIN + ms*16 + g + 8];
            #pragma unroll
            for (int ns = 0; ns < 4; ns++){
                int col = w*32 + ns*8 + tig*2;
                int rlo = msL*16 + g, rhi = rlo + 8;
                Bh[rlo*264 + col]     = tf32c(lrelu(accH[ms][ns][0] + blo));
                Bh[rlo*264 + col + 1] = tf32c(lrelu(accH[ms][ns][1] + blo));
                Bh[rhi*264 + col]     = tf32c(lrelu(accH[ms][ns][2] + bhi));
                Bh[rhi*264 + col + 1] = tf32c(lrelu(accH[ms][ns][3] + bhi));
            }
        }
        fill_A(pb + OFF_KOUT, 64, ck*32, As0, tid);
        __syncthreads();
        mma_tile(As0, Bh, accS, g, tig, w*32);
    }

    // epilogue
    #pragma unroll
    for (int ms = 0; ms < 4; ms++){
        int m = ms*16 + g;
        float bi0 = pb[OFF_BOUT + m]     + pb[OFF_BSK + m];
        float bi1 = pb[OFF_BOUT + m + 8] + pb[OFF_BSK + m + 8];
        #pragma unroll
        for (int ns = 0; ns < 4; ns++){
            int n = n0 + w*32 + ns*8 + 2*tig;
            float2 v0, v1;
            v0.x = accS[ms][ns][0] + bi0; v0.y = accS[ms][ns][1] + bi0;
            v1.x = accS[ms][ns][2] + bi1; v1.y = accS[ms][ns][3] + bi1;
            *(float2*)(outp + ((size_t)(b*NF + m))*HWD + n)     = v0;
            *(float2*)(outp + ((size_t)(b*NF + m + 8))*HWD + n) = v1;
        }
    }
}

// ---------------- freq + lat-copy fused ----------------
__global__ void __launch_bounds__(128) k_freqcat(const float* __restrict__ out,
                                                 const float* __restrict__ pe,
                                                 const float* __restrict__ lat,
                                                 float* __restrict__ cat){
    int b = blockIdx.y;
    if (blockIdx.x == 16){
        float4 v = *(const float4*)(lat + b*LATD + threadIdx.x*4);
        *(float4*)(cat + b*CATD + threadIdx.x*4) = v;
        return;
    }
    int c0 = blockIdx.x*4;
    const float* o0 = out + ((size_t)b*NF + c0)*HWD;
    float acc[4][24];
    #pragma unroll
    for (int ch = 0; ch < 4; ch++)
        #pragma unroll
        for (int f = 0; f < 24; f++) acc[ch][f] = 0.f;
    for (int p = threadIdx.x; p < HWD; p += 128){
        float ov0 = o0[p], ov1 = o0[HWD+p], ov2 = o0[2*HWD+p], ov3 = o0[3*HWD+p];
        #pragma unroll
        for (int f = 0; f < 24; f++){
            float pv = pe[f*HWD + p];
            acc[0][f] += ov0*pv; acc[1][f] += ov1*pv;
            acc[2][f] += ov2*pv; acc[3][f] += ov3*pv;
        }
    }
    __shared__ float red[4][4][24];
    int lane = threadIdx.x & 31, wrp = threadIdx.x >> 5;
    #pragma unroll
    for (int ch = 0; ch < 4; ch++)
        #pragma unroll
        for (int f = 0; f < 24; f++){
            float v = acc[ch][f];
            #pragma unroll
            for (int s = 16; s > 0; s >>= 1) v += __shfl_xor_sync(0xffffffffu, v, s);
            if (lane == 0) red[wrp][ch][f] = v;
        }
    __syncthreads();
    if (threadIdx.x < 96){
        int ch = threadIdx.x / 24, f = threadIdx.x % 24;
        float s = red[0][ch][f] + red[1][ch][f] + red[2][ch][f] + red[3][ch][f];
        cat[b*CATD + 512 + (c0+ch)*24 + f] = s * (1.f/4096.f);
    }
}

// ---------------- host orchestration ----------------
extern "C" void kernel_launch(void* const* d_in, const int* in_sizes, int n_in,
                              void* d_out, int out_size){
    const float* x      = (const float*)d_in[0];
    const float* inj    = (const float*)d_in[1];
    const float* w_in   = (const float*)d_in[2];
    const float* b_in   = (const float*)d_in[3];
    const float* fl_w1  = (const float*)d_in[4];
    const float* fl_b1  = (const float*)d_in[5];
    const float* fl_w2  = (const float*)d_in[6];
    const float* fl_b2  = (const float*)d_in[7];
    const float* fl_ws  = (const float*)d_in[8];
    const float* fl_bs  = (const float*)d_in[9];
    const float* dyn_w  = (const float*)d_in[10];
    const float* dyn_b  = (const float*)d_in[11];
    const float* pe     = (const float*)d_in[12];
    const float* otl_w1 = (const float*)d_in[13];
    const float* otl_b1 = (const float*)d_in[14];
    const float* otl_w2 = (const float*)d_in[15];
    const float* otl_b2 = (const float*)d_in[16];
    const float* otl_ws = (const float*)d_in[17];
    const float* otl_bs = (const float*)d_in[18];
    const float* ltl_w  = (const float*)d_in[19];
    const float* ltl_b  = (const float*)d_in[20];

    float *p_out0, *p_feat, *p_p, *p_injA, *p_injB, *p_latA, *p_latB;
    float *p_cat, *p_partW, *p_partM;
    cudaGetSymbolAddress((void**)&p_out0, g_out);
    cudaGetSymbolAddress((void**)&p_feat, g_feat);
    cudaGetSymbolAddress((void**)&p_p,    g_p);
    cudaGetSymbolAddress((void**)&p_injA, g_injA);
    cudaGetSymbolAddress((void**)&p_injB, g_injB);
    cudaGetSymbolAddress((void**)&p_latA, g_latA);
    cudaGetSymbolAddress((void**)&p_latB, g_latB);
    cudaGetSymbolAddress((void**)&p_cat,  g_cat);
    cudaGetSymbolAddress((void**)&p_partW, g_partW);
    cudaGetSymbolAddress((void**)&p_partM, g_partM);
    float* po[2] = { p_out0, p_out0 + (size_t)NB*NF*HWD };

    static cudaStream_t sW = nullptr, sO = nullptr;
    static cudaEvent_t ev0, evW[4], evD[4], evO[4];
    if (!sW){
        cudaStreamCreateWithFlags(&sW, cudaStreamNonBlocking);
        cudaStreamCreateWithFlags(&sO, cudaStreamNonBlocking);
        cudaEventCreateWithFlags(&ev0, cudaEventDisableTiming);
        for (int i = 0; i < 4; i++){
            cudaEventCreateWithFlags(&evW[i], cudaEventDisableTiming);
            cudaEventCreateWithFlags(&evD[i], cudaEventDisableTiming);
            cudaEventCreateWithFlags(&evO[i], cudaEventDisableTiming);
        }
        cudaFuncSetAttribute(k_dynF, cudaFuncAttributeMaxDynamicSharedMemorySize,
                             DYN_TOT*4);
    }

    // ---- main prologue (also positions gemm16_full at capture index 5) ----
    k_zero<<<16, 512>>>(p_latA);                       // launch 0
    k_init_out<<<NB*NF, 256>>>(x, w_in, b_in, po[0]);  // launch 1
    cudaEventRecord(ev0, 0);
    cudaStreamWaitEvent(sW, ev0, 0);
    cudaStreamWaitEvent(sO, ev0, 0);

    // ---- weight stream: 4 iterations of inj chain + p ----
    cudaMemcpyAsync(p_injA, inj, (size_t)NB*LATD*sizeof(float),
                    cudaMemcpyDeviceToDevice, sW);
    {
        float* injC = p_injA; float* injN = p_injB;
        for (int c = 0; c < 4; c++){
            gemm16_part2<<<dim3(4,8,2), 128, 0, sW>>>(injC, LATD,
                fl_w1, LATD, 0, fl_ws, LATD, 8, 64, p_partW, LDW);        // 2, ...
            gemm16_part_red<<<dim3(4,8), 128, 0, sW>>>(p_partW, LATD, 8, fl_b1,
                fl_w2, p_partW, LATD, 64, 16, LDW, LDW);                  // 3
            gemm16_reduce_fin<<<32, 256, 0, sW>>>(p_partW, 8, 16, fl_bs, fl_b2,
                injN, LATD, LDW);                                         // 4
            gemm16_full<<<(PD + 127)/128, 128, 0, sW>>>(injN, LATD, dyn_w, dyn_b,
                p_p + (size_t)c*NB*PD, PD);                               // 5 (c=0)
            cudaEventRecord(evW[c], sW);
            float* t = injC; injC = injN; injN = t;
        }
    }

    // ---- main image path ----
    float* latC = p_latA; float* latN = p_latB;

    for (int c = 0; c < 4; c++){
        k_perceive<<<dim3(NB*NF, 3), 256>>>(po[c & 1], p_feat);
        cudaStreamWaitEvent(0, evW[c], 0);
        if (c >= 2) cudaStreamWaitEvent(0, evO[c-2], 0);
        k_dynF<<<dim3(HWD/MTN, NB), 256, DYN_TOT*4>>>(p_p + (size_t)c*NB*PD,
                                                      p_feat, po[(c+1) & 1]);
        cudaEventRecord(evD[c], 0);

        cudaStreamWaitEvent(sO, evD[c], 0);
        k_freqcat<<<dim3(17, NB), 128, 0, sO>>>(po[(c+1) & 1], pe, latC, p_cat);
        const float* w1 = otl_w1 + (size_t)c*CATD*CATD;
        const float* b1 = otl_b1 + (size_t)c*CATD;
        const float* w2 = otl_w2 + (size_t)c*CATD*LATD;
        const float* b2 = otl_b2 + (size_t)c*LATD;
        const float* ws = otl_ws + (size_t)c*CATD*LATD;
        const float* bs = otl_bs + (size_t)c*LATD;
        gemm16_part2<<<dim3(16,8,2), 128, 0, sO>>>(p_cat, CATD,
            w1, CATD, 0, ws, LATD, 8, 256, p_partM, LDM);
        gemm16_part_red<<<dim3(4,8), 128, 0, sO>>>(p_partM, CATD, 8, b1,
            w2, p_partM, LATD, 256, 16, LDM, LDM);
        gemm16_reduce_fin<<<32, 256, 0, sO>>>(p_partM, 8, 16, bs, b2, latN, LATD, LDM);
        cudaEventRecord(evO[c], sO);

        float* t = latC; latC = latN; latN = t;
    }

    // ---- join + final ----
    cudaStreamWaitEvent(0, evO[3], 0);
    gemm16_part2<<<dim3(4,8,1), 128>>>(latC, LATD, ltl_w, LATD, 0,
                                       ltl_w, LATD, 0, 64, p_partW, LDW);
    gemm16_reduce_fin<<<32, 256>>>(p_partW, 0, 8, ltl_b, nullptr,
                                   (float*)d_out, LATD, LDW);
}

// round 17
// speedup vs baseline: 2.2630x; 1.1478x over previous
#include <cuda_runtime.h>
#include <cstdint>

#define NB   16
#define NF   64
#define LATD 512
#define IMG  64
#define HWD  4096
#define FIN  576
#define PD   78016
#define CATD 2048

#define OFF_KIN  0
#define OFF_BIN  36864
#define OFF_KOUT 36928
#define OFF_BOUT 41024
#define OFF_KSK  41088
#define OFF_BSK  77952

#define LDW  (16*LATD)
#define LDM  (16*CATD)
#define MTN  256

#define DYN_AS0 0
#define DYN_AS1 2304
#define DYN_BS  4608
#define DYN_BH  13056
#define DYN_TOT 21504   // *4 = 86016 B

typedef unsigned long long ull;

// ---------------- scratch ----------------
__device__ float g_out [2][NB*NF*HWD];
__device__ float g_feat[(size_t)NB*FIN*HWD];
__device__ float g_p   [4][NB*PD];
__device__ float g_injA[NB*LATD];
__device__ float g_injO[4][NB*LATD];
__device__ float g_latA[NB*LATD], g_latB[NB*LATD];
__device__ float g_cat [NB*CATD];
__device__ float g_partW[24*LDW];
__device__ float g_partM[24*LDM];

__device__ __forceinline__ float lrelu(float v){ return v > 0.f ? v : 0.2f*v; }
__device__ __forceinline__ uint32_t tf32c(float f){
    uint32_t r; asm("cvt.rna.tf32.f32 %0, %1;" : "=r"(r) : "f"(f)); return r;
}

// ---------------- init ----------------
__global__ void k_init_out(const float* __restrict__ x, const float* __restrict__ w_in,
                           const float* __restrict__ b_in, float* __restrict__ out){
    int b = blockIdx.x >> 6, o = blockIdx.x & 63;
    float w0 = w_in[o*3+0], w1 = w_in[o*3+1], w2 = w_in[o*3+2], bb = b_in[o];
    const float* xb = x + (size_t)b*3*HWD;
    float* ob = out + (size_t)blockIdx.x*HWD;
    for (int p = threadIdx.x; p < HWD; p += blockDim.x)
        ob[p] = w0*xb[p] + w1*xb[HWD+p] + w2*xb[2*HWD+p] + bb;
}
__global__ void k_zero(float* p){ p[blockIdx.x*512 + threadIdx.x] = 0.f; }

// ---------------- small GEMM family ----------------
__global__ void __launch_bounds__(128) gemm16_part2(
    const float* __restrict__ X, int K,
    const float* __restrict__ W0, int N0, int slot00,
    const float* __restrict__ W1, int N1, int slot01,
    int kc, float* __restrict__ Yp, int ldslot)
{
    const float* W = blockIdx.z ? W1 : W0;
    int N = blockIdx.z ? N1 : N0;
    int slot0 = blockIdx.z ? slot01 : slot00;
    if (blockIdx.x*128 >= N) return;
    __shared__ __align__(16) float Xs[256*16];
    int ks = blockIdx.y, k0 = ks*kc;
    int klen = min(kc, K - k0);
    for (int k = threadIdx.x; k < klen; k += 128){
        #pragma unroll
        for (int b = 0; b < 16; b++) Xs[k*16+b] = X[(size_t)b*K + k0 + k];
    }
    __syncthreads();
    int n = blockIdx.x*128 + threadIdx.x;
    if (n >= N) return;
    float acc[16];
    #pragma unroll
    for (int b = 0; b < 16; b++) acc[b] = 0.f;
    #pragma unroll 4
    for (int k = 0; k < klen; k++){
        float w = W[(size_t)(k0+k)*N + n];
        const float4* xp = (const float4*)(Xs + k*16);
        float4 x0 = xp[0], x1 = xp[1], x2 = xp[2], x3 = xp[3];
        acc[0]+=x0.x*w; acc[1]+=x0.y*w; acc[2]+=x0.z*w; acc[3]+=x0.w*w;
        acc[4]+=x1.x*w; acc[5]+=x1.y*w; acc[6]+=x1.z*w; acc[7]+=x1.w*w;
        acc[8]+=x2.x*w; acc[9]+=x2.y*w; acc[10]+=x2.z*w; acc[11]+=x2.w*w;
        acc[12]+=x3.x*w; acc[13]+=x3.y*w; acc[14]+=x3.z*w; acc[15]+=x3.w*w;
    }
    float* yp = Yp + (size_t)(slot0+ks)*ldslot;
    #pragma unroll
    for (int b = 0; b < 16; b++) yp[(size_t)b*N + n] = acc[b];
}

// parallel-fill version: Xs[k][b] = lrelu(b1[k] + sum over 8 slots)
__global__ void __launch_bounds__(128) gemm16_part_red(
    const float* __restrict__ Ypin, int Kin, const float* __restrict__ b1,
    const float* __restrict__ W, float* __restrict__ Yp, int N, int kc,
    int slot0, int ldin, int ldout)
{
    __shared__ __align__(16) float Xs[256*16];
    int ks = blockIdx.y, k0 = ks*kc;
    int klen = min(kc, Kin - k0);
    for (int idx = threadIdx.x; idx < klen*16; idx += 128){
        int k = idx % klen, b = idx / klen;
        const float* src = Ypin + (size_t)b*Kin + k0 + k;
        float s = b1[k0 + k];
        #pragma unroll
        for (int t = 0; t < 8; t++) s += src[(size_t)t*ldin];
        Xs[k*16+b] = lrelu(s);
    }
    __syncthreads();
    int n = blockIdx.x*128 + threadIdx.x;
    if (n >= N) return;
    float acc[16];
    #pragma unroll
    for (int b = 0; b < 16; b++) acc[b] = 0.f;
    #pragma unroll 4
    for (int k = 0; k < klen; k++){
        float w = W[(size_t)(k0+k)*N + n];
        const float4* xp = (const float4*)(Xs + k*16);
        float4 x0 = xp[0], x1 = xp[1], x2 = xp[2], x3 = xp[3];
        acc[0]+=x0.x*w; acc[1]+=x0.y*w; acc[2]+=x0.z*w; acc[3]+=x0.w*w;
        acc[4]+=x1.x*w; acc[5]+=x1.y*w; acc[6]+=x1.z*w; acc[7]+=x1.w*w;
        acc[8]+=x2.x*w; acc[9]+=x2.y*w; acc[10]+=x2.z*w; acc[11]+=x2.w*w;
        acc[12]+=x3.x*w; acc[13]+=x3.y*w; acc[14]+=x3.z*w; acc[15]+=x3.w*w;
    }
    float* yp = Yp + (size_t)(slot0+ks)*ldout;
    #pragma unroll
    for (int b = 0; b < 16; b++) yp[(size_t)b*N + n] = acc[b];
}

__global__ void gemm16_reduce_fin(const float* __restrict__ Yp, int s0, int cnt,
                                  const float* __restrict__ b1, const float* __restrict__ b2,
                                  float* __restrict__ Y, int N, int ldslot)
{
    int idx = blockIdx.x*256 + threadIdx.x;
    if (idx >= 16*N) return;
    int n = idx % N, b = idx / N;
    float s = 0.f;
    for (int t = 0; t < cnt; t++) s += Yp[(size_t)(s0+t)*ldslot + (size_t)b*N + n];
    if (b1) s += b1[n];
    if (b2) s += b2[n];
    Y[idx] = s;
}

__global__ void __launch_bounds__(128) gemm16_full(
    const float* __restrict__ X, int K, const float* __restrict__ W,
    const float* __restrict__ bias, float* __restrict__ Y, int N)
{
    __shared__ __align__(16) float Xs[512*16];
    for (int k = threadIdx.x; k < K; k += 128){
        #pragma unroll
        for (int b = 0; b < 16; b++) Xs[k*16+b] = X[(size_t)b*K + k];
    }
    __syncthreads();
    int n = blockIdx.x*128 + threadIdx.x;
    if (n >= N) return;
    float acc[16];
    #pragma unroll
    for (int b = 0; b < 16; b++) acc[b] = 0.f;
    #pragma unroll 8
    for (int k = 0; k < K; k++){
        float w = W[(size_t)k*N + n];
        const float4* xp = (const float4*)(Xs + k*16);
        float4 x0 = xp[0], x1 = xp[1], x2 = xp[2], x3 = xp[3];
        acc[0]+=x0.x*w; acc[1]+=x0.y*w; acc[2]+=x0.z*w; acc[3]+=x0.w*w;
        acc[4]+=x1.x*w; acc[5]+=x1.y*w; acc[6]+=x1.z*w; acc[7]+=x1.w*w;
        acc[8]+=x2.x*w; acc[9]+=x2.y*w; acc[10]+=x2.z*w; acc[11]+=x2.w*w;
        acc[12]+=x3.x*w; acc[13]+=x3.y*w; acc[14]+=x3.z*w; acc[15]+=x3.w*w;
    }
    float bv = bias[n];
    #pragma unroll
    for (int b = 0; b < 16; b++) Y[(size_t)b*N + n] = acc[b] + bv;
}

// ---------------- perceive + inorm: one group per block ----------------
__global__ void __launch_bounds__(256) k_perceive(const float* __restrict__ out,
                                                  float* __restrict__ feat){
    __shared__ float xs[64*64];
    __shared__ float rs1[8], rs2[8], bcast[2];
    int bcid = blockIdx.x, g = blockIdx.y;
    int b = bcid >> 6, c = bcid & 63;
    const float4* src = (const float4*)(out + (size_t)bcid*HWD);
    #pragma unroll
    for (int q = 0; q < 4; q++)
        *(float4*)(xs + 4*(q*256 + threadIdx.x)) = src[q*256 + threadIdx.x];
    __syncthreads();
    int lane = threadIdx.x & 31, wrp = threadIdx.x >> 5;
    float v[16];
    float s1 = 0.f, s2 = 0.f;
    int d = (g == 0) ? 0 : (1 << ((g-1) >> 1));
    int isX = ((g-1) & 1) == 0;
    #pragma unroll
    for (int t = 0; t < 16; t++){
        int p = threadIdx.x + t*256;
        int i = p >> 6, j = p & 63;
        float val;
        if (g == 0){
            val = xs[p];
        } else {
            int im = i-d, ip = i+d, jm = j-d, jp = j+d;
            bool imv = im >= 0, ipv = ip < 64, jmv = jm >= 0, jpv = jp < 64;
            if (isX){
                float t0 = ((imv&&jpv) ? xs[im*64+jp] : 0.f) - ((imv&&jmv) ? xs[im*64+jm] : 0.f);
                float t1 = (jpv ? xs[i*64+jp] : 0.f)         - (jmv ? xs[i*64+jm] : 0.f);
                float t2 = ((ipv&&jpv) ? xs[ip*64+jp] : 0.f) - ((ipv&&jmv) ? xs[ip*64+jm] : 0.f);
                val = 0.125f*(t0 + 2.f*t1 + t2);
            } else {
                float t0 = ((ipv&&jmv) ? xs[ip*64+jm] : 0.f) - ((imv&&jmv) ? xs[im*64+jm] : 0.f);
                float t1 = (ipv ? xs[ip*64+j] : 0.f)         - (imv ? xs[im*64+j] : 0.f);
                float t2 = ((ipv&&jpv) ? xs[ip*64+jp] : 0.f) - ((imv&&jpv) ? xs[im*64+jp] : 0.f);
                val = 0.125f*(t0 + 2.f*t1 + t2);
            }
        }
        v[t] = val; s1 += val; s2 += val*val;
    }
    #pragma unroll
    for (int s = 16; s > 0; s >>= 1){
        s1 += __shfl_xor_sync(0xffffffffu, s1, s);
        s2 += __shfl_xor_sync(0xffffffffu, s2, s);
    }
    if (lane == 0){ rs1[wrp] = s1; rs2[wrp] = s2; }
    __syncthreads();
    if (threadIdx.x == 0){
        float a = 0.f, q = 0.f;
        #pragma unroll
        for (int w = 0; w < 8; w++){ a += rs1[w]; q += rs2[w]; }
        float mean = a*(1.f/4096.f);
        float var  = q*(1.f/4096.f) - mean*mean;
        bcast[0] = mean; bcast[1] = rsqrtf(var + 1e-5f);
    }
    __syncthreads();
    float mean = bcast[0], inv = bcast[1];
    float* dst = feat + ((size_t)b*FIN + g*64 + c)*HWD;
    #pragma unroll
    for (int t = 0; t < 16; t++)
        dst[threadIdx.x + t*256] = (v[t]-mean)*inv;
}

// ---------------- fused dyn conv on mma.sync tf32 (unchanged) ----------------
__device__ __forceinline__ void fill_A(const float* __restrict__ A, int lda, int k0,
                                       uint32_t* As, int tid){
    #pragma unroll
    for (int q = 0; q < 2; q++){
        int fid = q*256 + tid;
        int row = fid >> 3, c4 = fid & 7;
        float4 v = *(const float4*)(A + (size_t)row*lda + k0 + c4*4);
        uint4 t; t.x = tf32c(v.x); t.y = tf32c(v.y); t.z = tf32c(v.z); t.w = tf32c(v.w);
        *(uint4*)(As + row*36 + c4*4) = t;
    }
}
__device__ __forceinline__ void fill_B(const float* __restrict__ B, int k0,
                                       uint32_t* Bs, int tid){
    #pragma unroll
    for (int q = 0; q < 8; q++){
        int fid = q*256 + tid;
        int row = fid >> 6, c4 = fid & 63;
        float4 v = *(const float4*)(B + (size_t)(k0+row)*HWD + c4*4);
        uint4 t; t.x = tf32c(v.x); t.y = tf32c(v.y); t.z = tf32c(v.z); t.w = tf32c(v.w);
        *(uint4*)(Bs + row*264 + c4*4) = t;
    }
}
__device__ __forceinline__ void mma_tile(const uint32_t* As, const uint32_t* Bs,
                                         float acc[4][4][4], int g, int tig, int nbase){
    #pragma unroll
    for (int k8 = 0; k8 < 4; k8++){
        uint32_t a[4][4];
        #pragma unroll
        for (int ms = 0; ms < 4; ms++){
            int r0 = ms*16 + g;
            a[ms][0] = As[r0*36 + k8*8 + tig];
            a[ms][1] = As[(r0+8)*36 + k8*8 + tig];
            a[ms][2] = As[r0*36 + k8*8 + tig + 4];
            a[ms][3] = As[(r0+8)*36 + k8*8 + tig + 4];
        }
        #pragma unroll
        for (int ns = 0; ns < 4; ns++){
            uint32_t b0 = Bs[(k8*8+tig)*264 + nbase + ns*8 + g];
            uint32_t b1 = Bs[(k8*8+tig+4)*264 + nbase + ns*8 + g];
            #pragma unroll
            for (int ms = 0; ms < 4; ms++){
                asm volatile("mma.sync.aligned.m16n8k8.row.col.f32.tf32.tf32.f32 "
                    "{%0,%1,%2,%3}, {%4,%5,%6,%7}, {%8,%9}, {%0,%1,%2,%3};"
                    : "+f"(acc[ms][ns][0]), "+f"(acc[ms][ns][1]),
                      "+f"(acc[ms][ns][2]), "+f"(acc[ms][ns][3])
                    : "r"(a[ms][0]), "r"(a[ms][1]), "r"(a[ms][2]), "r"(a[ms][3]),
                      "r"(b0), "r"(b1));
            }
        }
    }
}

__global__ void __launch_bounds__(256, 1) k_dynF(
    const float* __restrict__ p, const float* __restrict__ feat,
    float* __restrict__ outp)
{
    extern __shared__ uint32_t sm[];
    uint32_t* As0 = sm + DYN_AS0;
    uint32_t* As1 = sm + DYN_AS1;
    uint32_t* Bs  = sm + DYN_BS;
    uint32_t* Bh  = sm + DYN_BH;

    int b = blockIdx.y, n0 = blockIdx.x*MTN;
    int tid = threadIdx.x, w = tid >> 5, lane = tid & 31;
    int g = lane >> 2, tig = lane & 3;
    const float* pb = p + (size_t)b*PD;
    const float* featb = feat + (size_t)b*FIN*HWD + n0;

    float accH[4][4][4], accS[4][4][4];
    #pragma unroll
    for (int ms = 0; ms < 4; ms++)
        #pragma unroll
        for (int ns = 0; ns < 4; ns++)
            #pragma unroll
            for (int r = 0; r < 4; r++){ accH[ms][ns][r] = 0.f; accS[ms][ns][r] = 0.f; }

    for (int k0 = 0; k0 < FIN; k0 += 32){
        __syncthreads();
        fill_A(pb + OFF_KIN, FIN, k0, As0, tid);
        fill_A(pb + OFF_KSK, FIN, k0, As1, tid);
        fill_B(featb, k0, Bs, tid);
        __syncthreads();
        mma_tile(As0, Bs, accH, g, tig, w*32);
        mma_tile(As1, Bs, accS, g, tig, w*32);
    }

    #pragma unroll
    for (int ck = 0; ck < 2; ck++){
        __syncthreads();
        #pragma unroll
        for (int msL = 0; msL < 2; msL++){
            int ms = ck*2 + msL;
            float blo = pb[OFF_BIN + ms*16 + g];
            float bhi = pb[OFF_BIN + ms*16 + g + 8];
            #pragma unroll
            for (int ns = 0; ns < 4; ns++){
                int col = w*32 + ns*8 + tig*2;
                int rlo = msL*16 + g, rhi = rlo + 8;
                Bh[rlo*264 + col]     = tf32c(lrelu(accH[ms][ns][0] + blo));
                Bh[rlo*264 + col + 1] = tf32c(lrelu(accH[ms][ns][1] + blo));
                Bh[rhi*264 + col]     = tf32c(lrelu(accH[ms][ns][2] + bhi));
                Bh[rhi*264 + col + 1] = tf32c(lrelu(accH[ms][ns][3] + bhi));
            }
        }
        fill_A(pb + OFF_KOUT, 64, ck*32, As0, tid);
        __syncthreads();
        mma_tile(As0, Bh, accS, g, tig, w*32);
    }

    #pragma unroll
    for (int ms = 0; ms < 4; ms++){
        int m = ms*16 + g;
        float bi0 = pb[OFF_BOUT + m]     + pb[OFF_BSK + m];
        float bi1 = pb[OFF_BOUT + m + 8] + pb[OFF_BSK + m + 8];
        #pragma unroll
        for (int ns = 0; ns < 4; ns++){
            int n = n0 + w*32 + ns*8 + 2*tig;
            float2 v0, v1;
            v0.x = accS[ms][ns][0] + bi0; v0.y = accS[ms][ns][1] + bi0;
            v1.x = accS[ms][ns][2] + bi1; v1.y = accS[ms][ns][3] + bi1;
            *(float2*)(outp + ((size_t)(b*NF + m))*HWD + n)     = v0;
            *(float2*)(outp + ((size_t)(b*NF + m + 8))*HWD + n) = v1;
        }
    }
}

// ---------------- freq + lat-copy fused ----------------
__global__ void __launch_bounds__(128) k_freqcat(const float* __restrict__ out,
                                                 const float* __restrict__ pe,
                                                 const float* __restrict__ lat,
                                                 float* __restrict__ cat){
    int b = blockIdx.y;
    if (blockIdx.x == 16){
        float4 v = *(const float4*)(lat + b*LATD + threadIdx.x*4);
        *(float4*)(cat + b*CATD + threadIdx.x*4) = v;
        return;
    }
    int c0 = blockIdx.x*4;
    const float* o0 = out + ((size_t)b*NF + c0)*HWD;
    float acc[4][24];
    #pragma unroll
    for (int ch = 0; ch < 4; ch++)
        #pragma unroll
        for (int f = 0; f < 24; f++) acc[ch][f] = 0.f;
    for (int p = threadIdx.x; p < HWD; p += 128){
        float ov0 = o0[p], ov1 = o0[HWD+p], ov2 = o0[2*HWD+p], ov3 = o0[3*HWD+p];
        #pragma unroll
        for (int f = 0; f < 24; f++){
            float pv = pe[f*HWD + p];
            acc[0][f] += ov0*pv; acc[1][f] += ov1*pv;
            acc[2][f] += ov2*pv; acc[3][f] += ov3*pv;
        }
    }
    __shared__ float red[4][4][24];
    int lane = threadIdx.x & 31, wrp = threadIdx.x >> 5;
    #pragma unroll
    for (int ch = 0; ch < 4; ch++)
        #pragma unroll
        for (int f = 0; f < 24; f++){
            float v = acc[ch][f];
            #pragma unroll
            for (int s = 16; s > 0; s >>= 1) v += __shfl_xor_sync(0xffffffffu, v, s);
            if (lane == 0) red[wrp][ch][f] = v;
        }
    __syncthreads();
    if (threadIdx.x < 96){
        int ch = threadIdx.x / 24, f = threadIdx.x % 24;
        float s = red[0][ch][f] + red[1][ch][f] + red[2][ch][f] + red[3][ch][f];
        cat[b*CATD + 512 + (c0+ch)*24 + f] = s * (1.f/4096.f);
    }
}

// ---------------- host orchestration (4 streams) ----------------
extern "C" void kernel_launch(void* const* d_in, const int* in_sizes, int n_in,
                              void* d_out, int out_size){
    const float* x      = (const float*)d_in[0];
    const float* inj    = (const float*)d_in[1];
    const float* w_in   = (const float*)d_in[2];
    const float* b_in   = (const float*)d_in[3];
    const float* fl_w1  = (const float*)d_in[4];
    const float* fl_b1  = (const float*)d_in[5];
    const float* fl_w2  = (const float*)d_in[6];
    const float* fl_b2  = (const float*)d_in[7];
    const float* fl_ws  = (const float*)d_in[8];
    const float* fl_bs  = (const float*)d_in[9];
    const float* dyn_w  = (const float*)d_in[10];
    const float* dyn_b  = (const float*)d_in[11];
    const float* pe     = (const float*)d_in[12];
    const float* otl_w1 = (const float*)d_in[13];
    const float* otl_b1 = (const float*)d_in[14];
    const float* otl_w2 = (const float*)d_in[15];
    const float* otl_b2 = (const float*)d_in[16];
    const float* otl_ws = (const float*)d_in[17];
    const float* otl_bs = (const float*)d_in[18];
    const float* ltl_w  = (const float*)d_in[19];
    const float* ltl_b  = (const float*)d_in[20];

    float *p_out0, *p_feat, *p_p, *p_injA, *p_injO, *p_latA, *p_latB;
    float *p_cat, *p_partW, *p_partM;
    cudaGetSymbolAddress((void**)&p_out0, g_out);
    cudaGetSymbolAddress((void**)&p_feat, g_feat);
    cudaGetSymbolAddress((void**)&p_p,    g_p);
    cudaGetSymbolAddress((void**)&p_injA, g_injA);
    cudaGetSymbolAddress((void**)&p_injO, g_injO);
    cudaGetSymbolAddress((void**)&p_latA, g_latA);
    cudaGetSymbolAddress((void**)&p_latB, g_latB);
    cudaGetSymbolAddress((void**)&p_cat,  g_cat);
    cudaGetSymbolAddress((void**)&p_partW, g_partW);
    cudaGetSymbolAddress((void**)&p_partM, g_partM);
    float* po[2] = { p_out0, p_out0 + (size_t)NB*NF*HWD };

    static cudaStream_t sW = nullptr, sO = nullptr, sF = nullptr;
    static cudaEvent_t ev0, evI[4], evW[4], evD[4], evO[4];
    if (!sW){
        cudaStreamCreateWithFlags(&sW, cudaStreamNonBlocking);
        cudaStreamCreateWithFlags(&sO, cudaStreamNonBlocking);
        cudaStreamCreateWithFlags(&sF, cudaStreamNonBlocking);
        cudaEventCreateWithFlags(&ev0, cudaEventDisableTiming);
        for (int i = 0; i < 4; i++){
            cudaEventCreateWithFlags(&evI[i], cudaEventDisableTiming);
            cudaEventCreateWithFlags(&evW[i], cudaEventDisableTiming);
            cudaEventCreateWithFlags(&evD[i], cudaEventDisableTiming);
            cudaEventCreateWithFlags(&evO[i], cudaEventDisableTiming);
        }
        cudaFuncSetAttribute(k_dynF, cudaFuncAttributeMaxDynamicSharedMemorySize,
                             DYN_TOT*4);
    }

    // ---- prologue ----
    k_zero<<<16, 512>>>(p_latA);
    k_init_out<<<NB*NF, 256>>>(x, w_in, b_in, po[0]);
    cudaEventRecord(ev0, 0);
    cudaStreamWaitEvent(sW, ev0, 0);
    cudaStreamWaitEvent(sO, ev0, 0);
    cudaStreamWaitEvent(sF, ev0, 0);

    // ---- weight streams: inj chain on sW; dyn_w projection on sF ----
    cudaMemcpyAsync(p_injA, inj, (size_t)NB*LATD*sizeof(float),
                    cudaMemcpyDeviceToDevice, sW);
    {
        const float* injC = p_injA;
        for (int c = 0; c < 4; c++){
            float* injN = p_injO + (size_t)c*NB*LATD;
            gemm16_part2<<<dim3(4,8,2), 128, 0, sW>>>(injC, LATD,
                fl_w1, LATD, 0, fl_ws, LATD, 8, 64, p_partW, LDW);
            gemm16_part_red<<<dim3(4,8), 128, 0, sW>>>(p_partW, LATD, fl_b1,
                fl_w2, p_partW, LATD, 64, 16, LDW, LDW);
            gemm16_reduce_fin<<<32, 256, 0, sW>>>(p_partW, 8, 16, fl_bs, fl_b2,
                injN, LATD, LDW);
            cudaEventRecord(evI[c], sW);

            cudaStreamWaitEvent(sF, evI[c], 0);
            gemm16_full<<<(PD + 127)/128, 128, 0, sF>>>(injN, LATD, dyn_w, dyn_b,
                p_p + (size_t)c*NB*PD, PD);
            cudaEventRecord(evW[c], sF);
            injC = injN;
        }
    }

    // ---- main image path ----
    float* latC = p_latA; float* latN = p_latB;

    for (int c = 0; c < 4; c++){
        k_perceive<<<dim3(NB*NF, 9), 256>>>(po[c & 1], p_feat);
        cudaStreamWaitEvent(0, evW[c], 0);
        if (c >= 2) cudaStreamWaitEvent(0, evO[c-2], 0);
        k_dynF<<<dim3(HWD/MTN, NB), 256, DYN_TOT*4>>>(p_p + (size_t)c*NB*PD,
                                                      p_feat, po[(c+1) & 1]);
        cudaEventRecord(evD[c], 0);

        cudaStreamWaitEvent(sO, evD[c], 0);
        k_freqcat<<<dim3(17, NB), 128, 0, sO>>>(po[(c+1) & 1], pe, latC, p_cat);
        const float* w1 = otl_w1 + (size_t)c*CATD*CATD;
        const float* b1 = otl_b1 + (size_t)c*CATD;
        const float* w2 = otl_w2 + (size_t)c*CATD*LATD;
        const float* b2 = otl_b2 + (size_t)c*LATD;
        const float* ws = otl_ws + (size_t)c*CATD*LATD;
        const float* bs = otl_bs + (size_t)c*LATD;
        gemm16_part2<<<dim3(16,8,2), 128, 0, sO>>>(p_cat, CATD,
            w1, CATD, 0, ws, LATD, 8, 256, p_partM, LDM);
        gemm16_part_red<<<dim3(4,8), 128, 0, sO>>>(p_partM, CATD, b1,
            w2, p_partM, LATD, 256, 16, LDM, LDM);
        gemm16_reduce_fin<<<32, 256, 0, sO>>>(p_partM, 8, 16, bs, b2, latN, LATD, LDM);
        cudaEventRecord(evO[c], sO);

        float* t = latC; latC = latN; latN = t;
    }

    // ---- join + final ----
    cudaStreamWaitEvent(0, evO[3], 0);
    gemm16_part2<<<dim3(4,8,1), 128>>>(latC, LATD, ltl_w, LATD, 0,
                                       ltl_w, LATD, 0, 64, p_partW, LDW);
    gemm16_reduce_fin<<<32, 256>>>(p_partW, 0, 8, ltl_b, nullptr,
                                   (float*)d_out, LATD, LDW);
}